// round 1
// baseline (speedup 1.0000x reference)
#include <cuda_runtime.h>
#include <cuda_bf16.h>
#include <math.h>

// ---------------- problem constants ----------------
#define DIM      192
#define HEADS    6
#define HD       32
#define HIDDEN   768
#define NLON     15
#define NW       64
#define NTOK     144          // tokens per window
#define WTOK     138240       // NLON*NW*NTOK padded window tokens
#define LTOK     131040       // 8*91*180 real tokens
#define EPSLN    1e-5f

// ---------------- device scratch (no allocation allowed) ----------------
__device__ float g_h   [(size_t)WTOK * DIM];     // LN1 + windowed
__device__ float g_qkv [(size_t)WTOK * 3 * DIM]; // qkv
__device__ float g_att [(size_t)WTOK * DIM];     // attention output
__device__ float g_proj[(size_t)WTOK * DIM];     // proj output (window layout)
__device__ float g_x1  [(size_t)LTOK * DIM];     // residual 1
__device__ float g_h2  [(size_t)LTOK * DIM];     // LN2 output
__device__ float g_fc1 [(size_t)LTOK * HIDDEN];  // fc1+gelu

// ---------------- LN helpers (192 threads / block, 6 warps) ----------------
__device__ __forceinline__ void block_meanvar_192(float v, float& mean, float& var) {
    float s = v, q = v * v;
    #pragma unroll
    for (int o = 16; o > 0; o >>= 1) {
        s += __shfl_down_sync(0xffffffffu, s, o);
        q += __shfl_down_sync(0xffffffffu, q, o);
    }
    __shared__ float sm_s[6], sm_q[6], sm_bc[2];
    int wid = threadIdx.x >> 5, lane = threadIdx.x & 31;
    if (lane == 0) { sm_s[wid] = s; sm_q[wid] = q; }
    __syncthreads();
    if (threadIdx.x == 0) {
        float ts = 0.f, tq = 0.f;
        #pragma unroll
        for (int i = 0; i < 6; i++) { ts += sm_s[i]; tq += sm_q[i]; }
        float m = ts * (1.0f / 192.0f);
        sm_bc[0] = m;
        sm_bc[1] = tq * (1.0f / 192.0f) - m * m;
    }
    __syncthreads();
    mean = sm_bc[0];
    var  = sm_bc[1];
}

// ---------------- kernel 1: LN1 + pad + roll + window partition ----------------
__global__ void ln1_window_kernel(const float* __restrict__ x,
                                  const float* __restrict__ w1,
                                  const float* __restrict__ b1) {
    int t = blockIdx.x;          // window token 0..WTOK-1
    int c = threadIdx.x;         // 0..191
    int ilon = t / (NW * NTOK);
    int rem  = t % (NW * NTOK);
    int iw = rem / NTOK, n = rem % NTOK;
    int ipl = iw >> 4, ilat = iw & 15;
    int z = n / 72, hh = (n / 12) % 6, ww = n % 12;
    int pl_r  = ipl * 2 + z;
    int lat_r = ilat * 6 + hh;
    int lon_r = ilon * 12 + ww;
    int pl_s  = (pl_r + 1) & 7;
    int lat_p = lat_r + 3; if (lat_p >= 96) lat_p -= 96;
    int lat_s = lat_p - 2;
    int lon_s = lon_r + 6; if (lon_s >= 180) lon_s -= 180;

    float out = 0.f;
    if (lat_s >= 0 && lat_s < 91) {
        size_t src = ((size_t)(pl_s * 91 + lat_s) * 180 + lon_s) * DIM;
        float v = x[src + c];
        float mean, var;
        block_meanvar_192(v, mean, var);
        out = (v - mean) * rsqrtf(var + EPSLN) * w1[c] + b1[c];
    }
    g_h[(size_t)t * DIM + c] = out;
}

// ---------------- generic fp32 GEMM: C = A[M,K] * W[N,K]^T + bias (+gelu)(+res) ----------------
// 64x64 tile, BK=16, 256 threads, 4x4 microtile
__global__ void gemm_kernel(const float* __restrict__ A,
                            const float* __restrict__ W,
                            const float* __restrict__ bias,
                            const float* __restrict__ res,
                            float* __restrict__ C,
                            int M, int N, int K, int act) {
    __shared__ float As[16][68];
    __shared__ float Bs[16][68];
    int tid = threadIdx.x;
    int tx = tid & 15, ty = tid >> 4;
    int row0 = blockIdx.y * 64;
    int col0 = blockIdx.x * 64;
    int lr = tid >> 2;          // 0..63
    int lk = (tid & 3) * 4;     // 0,4,8,12
    float acc[4][4] = {};

    for (int k0 = 0; k0 < K; k0 += 16) {
        int gr = row0 + lr;
        float4 a4 = make_float4(0.f, 0.f, 0.f, 0.f);
        if (gr < M) a4 = *(const float4*)(A + (size_t)gr * K + k0 + lk);
        As[lk + 0][lr] = a4.x; As[lk + 1][lr] = a4.y;
        As[lk + 2][lr] = a4.z; As[lk + 3][lr] = a4.w;
        float4 b4 = *(const float4*)(W + (size_t)(col0 + lr) * K + k0 + lk);
        Bs[lk + 0][lr] = b4.x; Bs[lk + 1][lr] = b4.y;
        Bs[lk + 2][lr] = b4.z; Bs[lk + 3][lr] = b4.w;
        __syncthreads();
        #pragma unroll
        for (int k = 0; k < 16; k++) {
            float a[4], b[4];
            *(float4*)a = *(const float4*)&As[k][ty * 4];
            *(float4*)b = *(const float4*)&Bs[k][tx * 4];
            #pragma unroll
            for (int i = 0; i < 4; i++)
                #pragma unroll
                for (int j = 0; j < 4; j++)
                    acc[i][j] += a[i] * b[j];
        }
        __syncthreads();
    }

    #pragma unroll
    for (int i = 0; i < 4; i++) {
        int r = row0 + ty * 4 + i;
        if (r >= M) continue;
        #pragma unroll
        for (int j = 0; j < 4; j++) {
            int c = col0 + tx * 4 + j;
            float v = acc[i][j] + bias[c];
            if (act == 1)
                v = 0.5f * v * (1.0f + erff(v * 0.70710678118654752440f));
            if (res) v += res[(size_t)r * N + c];
            C[(size_t)r * N + c] = v;
        }
    }
}

// ---------------- kernel 3: windowed attention, one block per (window, head) ----------------
// smem: Q/K/V (3*4608 f), scores 144*145 f, bias col 3312 f, index arrays 3*144 int
#define ATTN_SMEM_BYTES ((4608 * 3 + 144 * 145 + 3312) * 4 + 144 * 3 * 4)

__global__ void attn_kernel(const float* __restrict__ bias_table) {
    extern __shared__ float sm[];
    float* Qs = sm;
    float* Ks = Qs + 4608;
    float* Vs = Ks + 4608;
    float* Ss = Vs + 4608;         // stride 145 rows
    float* sB = Ss + 144 * 145;    // 3312
    int*   cM = (int*)(sB + 3312);
    int*   rB = cM + 144;
    int*   rG = rB + 144;

    int blk  = blockIdx.x;
    int g    = blk / HEADS;
    int head = blk % HEADS;
    int ilon = g / NW, iw = g % NW;
    int ipl = iw >> 4, ilat = iw & 15;
    int tid = threadIdx.x;  // 160
    size_t base = (size_t)g * NTOK;
    const float scale = 0.17677669529663687f;  // 1/sqrt(32)

    for (int i = tid; i < 4608; i += 160) {
        int n = i >> 5, d = i & 31;
        size_t o = (base + n) * (3 * DIM) + head * HD + d;
        Qs[i] = g_qkv[o] * scale;
        Ks[i] = g_qkv[o + DIM];
        Vs[i] = g_qkv[o + 2 * DIM];
    }
    for (int i = tid; i < 3312; i += 160)
        sB[i] = bias_table[(size_t)i * (NW * HEADS) + iw * HEADS + head];
    for (int i = tid; i < 144; i += 160) {
        int z = i / 72, h = (i / 12) % 6, w = i % 12;
        cM[i] = 1656 * z + 138 * h - w;
        rB[i] = 828 * z + 23 * h + w + 11;
        int pl = ipl * 2 + z, lat = ilat * 6 + h, lon = ilon * 12 + w;
        rG[i] = (pl < 6 ? 0 : (pl < 7 ? 1 : 2)) * 9
              + (lat < 90 ? 0 : (lat < 93 ? 1 : 2)) * 3
              + (lon < 174 ? 0 : 1);
    }
    __syncthreads();

    if (tid < 144) {
        float q[HD];
        #pragma unroll
        for (int d = 0; d < HD; d++) q[d] = Qs[tid * HD + d];
        int rb = rB[tid], rg = rG[tid];
        float* srow = Ss + tid * 145;
        float mx = -1e30f;
        for (int m = 0; m < 144; m++) {
            const float* kp = Ks + m * HD;
            float s = 0.f;
            #pragma unroll
            for (int d = 0; d < HD; d++) s += q[d] * kp[d];
            s += sB[rb + cM[m]];
            if (rG[m] != rg) s -= 100.0f;
            srow[m] = s;
            mx = fmaxf(mx, s);
        }
        float denom = 0.f;
        for (int m = 0; m < 144; m++) {
            float p = expf(srow[m] - mx);
            srow[m] = p;
            denom += p;
        }
        float inv = 1.0f / denom;
        float out[HD];
        #pragma unroll
        for (int d = 0; d < HD; d++) out[d] = 0.f;
        for (int m = 0; m < 144; m++) {
            float p = srow[m];
            const float* vp = Vs + m * HD;
            #pragma unroll
            for (int d = 0; d < HD; d++) out[d] += p * vp[d];
        }
        size_t o = (base + tid) * DIM + head * HD;
        #pragma unroll
        for (int d = 0; d < HD; d++) g_att[o + d] = out[d] * inv;
    }
}

// ---------------- kernel 5: inverse window scatter + residual + LN2 ----------------
__global__ void resid_ln2_kernel(const float* __restrict__ x,
                                 const float* __restrict__ w2,
                                 const float* __restrict__ b2) {
    int t = blockIdx.x;     // original token 0..LTOK-1
    int c = threadIdx.x;
    int lon = t % 180;
    int lat = (t / 180) % 91;
    int pl  = t / (180 * 91);
    int pl_r  = (pl + 7) & 7;                 // (pl-1) mod 8
    int lat_r = lat - 1; if (lat_r < 0) lat_r += 96;  // (lat+2-3) mod 96
    int lon_r = lon - 6; if (lon_r < 0) lon_r += 180;
    int ilon = lon_r / 12, ww = lon_r % 12;
    int ipl = pl_r >> 1,  z  = pl_r & 1;
    int ilat = lat_r / 6, hh = lat_r % 6;
    size_t wt = (size_t)(ilon * NW + ipl * 16 + ilat) * NTOK + z * 72 + hh * 12 + ww;

    float v = x[(size_t)t * DIM + c] + g_proj[wt * DIM + c];
    g_x1[(size_t)t * DIM + c] = v;
    float mean, var;
    block_meanvar_192(v, mean, var);
    g_h2[(size_t)t * DIM + c] = (v - mean) * rsqrtf(var + EPSLN) * w2[c] + b2[c];
}

// ---------------- launcher ----------------
extern "C" void kernel_launch(void* const* d_in, const int* in_sizes, int n_in,
                              void* d_out, int out_size) {
    const float* x     = (const float*)d_in[0];
    const float* n1w   = (const float*)d_in[1];
    const float* n1b   = (const float*)d_in[2];
    const float* qkvw  = (const float*)d_in[3];
    const float* qkvb  = (const float*)d_in[4];
    const float* btab  = (const float*)d_in[5];
    const float* projw = (const float*)d_in[6];
    const float* projb = (const float*)d_in[7];
    const float* n2w   = (const float*)d_in[8];
    const float* n2b   = (const float*)d_in[9];
    const float* fc1w  = (const float*)d_in[10];
    const float* fc1b  = (const float*)d_in[11];
    const float* fc2w  = (const float*)d_in[12];
    const float* fc2b  = (const float*)d_in[13];
    float* out = (float*)d_out;

    float *p_h, *p_qkv, *p_att, *p_proj, *p_x1, *p_h2, *p_fc1;
    cudaGetSymbolAddress((void**)&p_h,    g_h);
    cudaGetSymbolAddress((void**)&p_qkv,  g_qkv);
    cudaGetSymbolAddress((void**)&p_att,  g_att);
    cudaGetSymbolAddress((void**)&p_proj, g_proj);
    cudaGetSymbolAddress((void**)&p_x1,   g_x1);
    cudaGetSymbolAddress((void**)&p_h2,   g_h2);
    cudaGetSymbolAddress((void**)&p_fc1,  g_fc1);

    cudaFuncSetAttribute(attn_kernel,
                         cudaFuncAttributeMaxDynamicSharedMemorySize,
                         ATTN_SMEM_BYTES);

    // 1. LN1 + window partition
    ln1_window_kernel<<<WTOK, DIM>>>(x, n1w, n1b);

    // 2. QKV gemm: [WTOK,192] x [576,192]^T
    gemm_kernel<<<dim3(576 / 64, WTOK / 64), 256>>>(
        p_h, qkvw, qkvb, nullptr, p_qkv, WTOK, 3 * DIM, DIM, 0);

    // 3. attention per (window, head)
    attn_kernel<<<NLON * NW * HEADS, 160, ATTN_SMEM_BYTES>>>(btab);

    // 4. proj gemm: [WTOK,192] x [192,192]^T
    gemm_kernel<<<dim3(DIM / 64, WTOK / 64), 256>>>(
        p_att, projw, projb, nullptr, p_proj, WTOK, DIM, DIM, 0);

    // 5. scatter + residual + LN2
    resid_ln2_kernel<<<LTOK, DIM>>>(x, n2w, n2b);

    // 6. fc1 gemm + exact GELU: [LTOK,192] x [768,192]^T
    gemm_kernel<<<dim3(HIDDEN / 64, (LTOK + 63) / 64), 256>>>(
        p_h2, fc1w, fc1b, nullptr, p_fc1, LTOK, HIDDEN, DIM, 1);

    // 7. fc2 gemm + residual: [LTOK,768] x [192,768]^T + x1 -> out
    gemm_kernel<<<dim3(DIM / 64, (LTOK + 63) / 64), 256>>>(
        p_fc1, fc2w, fc2b, p_x1, out, LTOK, DIM, HIDDEN, 0);
}

// round 2
// speedup vs baseline: 1.5000x; 1.5000x over previous
#include <cuda_runtime.h>
#include <cuda_bf16.h>
#include <math.h>
#include <stdint.h>

// ---------------- problem constants ----------------
#define DIM      192
#define HEADS    6
#define HD       32
#define HIDDEN   768
#define NLON     15
#define NW       64
#define NTOK     144          // tokens per window
#define WTOK     138240       // NLON*NW*NTOK padded window tokens
#define LTOK     131040       // 8*91*180 real tokens
#define EPSLN    1e-5f

// ---------------- device scratch (no allocation allowed) ----------------
__device__ float g_h   [(size_t)WTOK * DIM];     // LN1 + windowed
__device__ float g_qkv [(size_t)WTOK * 3 * DIM]; // qkv
__device__ float g_att [(size_t)WTOK * DIM];     // attention output
__device__ float g_proj[(size_t)WTOK * DIM];     // proj output (window layout)
__device__ float g_x1  [(size_t)LTOK * DIM];     // residual 1
__device__ float g_h2  [(size_t)LTOK * DIM];     // LN2 output
__device__ float g_fc1 [(size_t)LTOK * HIDDEN];  // fc1+gelu

// ---------------- LN helpers (192 threads / block, 6 warps) ----------------
__device__ __forceinline__ void block_meanvar_192(float v, float& mean, float& var) {
    float s = v, q = v * v;
    #pragma unroll
    for (int o = 16; o > 0; o >>= 1) {
        s += __shfl_down_sync(0xffffffffu, s, o);
        q += __shfl_down_sync(0xffffffffu, q, o);
    }
    __shared__ float sm_s[6], sm_q[6], sm_bc[2];
    int wid = threadIdx.x >> 5, lane = threadIdx.x & 31;
    if (lane == 0) { sm_s[wid] = s; sm_q[wid] = q; }
    __syncthreads();
    if (threadIdx.x == 0) {
        float ts = 0.f, tq = 0.f;
        #pragma unroll
        for (int i = 0; i < 6; i++) { ts += sm_s[i]; tq += sm_q[i]; }
        float m = ts * (1.0f / 192.0f);
        sm_bc[0] = m;
        sm_bc[1] = tq * (1.0f / 192.0f) - m * m;
    }
    __syncthreads();
    mean = sm_bc[0];
    var  = sm_bc[1];
}

// ---------------- kernel 1: LN1 + pad + roll + window partition ----------------
__global__ void ln1_window_kernel(const float* __restrict__ x,
                                  const float* __restrict__ w1,
                                  const float* __restrict__ b1) {
    int t = blockIdx.x;          // window token 0..WTOK-1
    int c = threadIdx.x;         // 0..191
    int ilon = t / (NW * NTOK);
    int rem  = t % (NW * NTOK);
    int iw = rem / NTOK, n = rem % NTOK;
    int ipl = iw >> 4, ilat = iw & 15;
    int z = n / 72, hh = (n / 12) % 6, ww = n % 12;
    int pl_r  = ipl * 2 + z;
    int lat_r = ilat * 6 + hh;
    int lon_r = ilon * 12 + ww;
    int pl_s  = (pl_r + 1) & 7;
    int lat_p = lat_r + 3; if (lat_p >= 96) lat_p -= 96;
    int lat_s = lat_p - 2;
    int lon_s = lon_r + 6; if (lon_s >= 180) lon_s -= 180;

    float out = 0.f;
    if (lat_s >= 0 && lat_s < 91) {
        size_t src = ((size_t)(pl_s * 91 + lat_s) * 180 + lon_s) * DIM;
        float v = x[src + c];
        float mean, var;
        block_meanvar_192(v, mean, var);
        out = (v - mean) * rsqrtf(var + EPSLN) * w1[c] + b1[c];
    }
    g_h[(size_t)t * DIM + c] = out;
}

// ---------------- tf32 tensor-core GEMM ----------------
// C[M,N] = A[M,K] * W[N,K]^T + bias (+gelu)(+res)
// tile 128x64, BK=16, 256 threads = 8 warps (4m x 2n), warp tile 32x32
// mma.sync.aligned.m16n8k8.row.col.f32.tf32.tf32.f32
#define SA 136   // As row stride (136 % 32 == 8 -> conflict-free frag loads)
#define SB 72    // Bs row stride (72  % 32 == 8)

__device__ __forceinline__ uint32_t f2tf(float x) {
    uint32_t u;
    asm("cvt.rna.tf32.f32 %0, %1;" : "=r"(u) : "f"(x));
    return u;
}

__device__ __forceinline__ void mma_tf32(float c[4], const uint32_t a[4], const uint32_t b[2]) {
    asm volatile(
        "mma.sync.aligned.m16n8k8.row.col.f32.tf32.tf32.f32 "
        "{%0,%1,%2,%3}, {%4,%5,%6,%7}, {%8,%9}, {%0,%1,%2,%3};"
        : "+f"(c[0]), "+f"(c[1]), "+f"(c[2]), "+f"(c[3])
        : "r"(a[0]), "r"(a[1]), "r"(a[2]), "r"(a[3]), "r"(b[0]), "r"(b[1]));
}

__global__ __launch_bounds__(256) void gemm_tf32_kernel(
        const float* __restrict__ A,
        const float* __restrict__ W,
        const float* __restrict__ bias,
        const float* __restrict__ res,
        float* __restrict__ C,
        int M, int N, int K, int act) {
    __shared__ uint32_t As[16][SA];
    __shared__ uint32_t Bs[16][SB];

    const int tid  = threadIdx.x;
    const int warp = tid >> 5, lane = tid & 31;
    const int wm = warp & 3, wn = warp >> 2;     // 4 x 2 warp grid
    const int g = lane >> 2, tig = lane & 3;
    const int row0 = blockIdx.y * 128;
    const int col0 = blockIdx.x * 64;

    // global->smem load indices
    const int am = tid >> 2;               // 0..63 (rows, +64 on 2nd chunk)
    const int ak = (tid & 3) * 4;          // k quad
    const int bn = tid >> 2;               // 0..63
    const int bk = (tid & 3) * 4;

    float acc[2][4][4] = {};
    float4 aR[2], bR;

    // prefetch first tile
    {
        int r0 = row0 + am, r1 = row0 + am + 64;
        aR[0] = (r0 < M) ? *(const float4*)(A + (size_t)r0 * K + ak)
                         : make_float4(0.f, 0.f, 0.f, 0.f);
        aR[1] = (r1 < M) ? *(const float4*)(A + (size_t)r1 * K + ak)
                         : make_float4(0.f, 0.f, 0.f, 0.f);
        bR = *(const float4*)(W + (size_t)(col0 + bn) * K + bk);
    }

    for (int k0 = 0; k0 < K; k0 += 16) {
        // commit prefetched tile to smem (tf32-converted)
        {
            const float* a0 = (const float*)&aR[0];
            const float* a1 = (const float*)&aR[1];
            const float* bb = (const float*)&bR;
            #pragma unroll
            for (int j = 0; j < 4; j++) {
                As[ak + j][am]      = f2tf(a0[j]);
                As[ak + j][am + 64] = f2tf(a1[j]);
                Bs[bk + j][bn]      = f2tf(bb[j]);
            }
        }
        __syncthreads();

        // prefetch next tile
        if (k0 + 16 < K) {
            int r0 = row0 + am, r1 = row0 + am + 64;
            aR[0] = (r0 < M) ? *(const float4*)(A + (size_t)r0 * K + k0 + 16 + ak)
                             : make_float4(0.f, 0.f, 0.f, 0.f);
            aR[1] = (r1 < M) ? *(const float4*)(A + (size_t)r1 * K + k0 + 16 + ak)
                             : make_float4(0.f, 0.f, 0.f, 0.f);
            bR = *(const float4*)(W + (size_t)(col0 + bn) * K + k0 + 16 + bk);
        }

        // compute 2 k-steps of 8
        #pragma unroll
        for (int ks = 0; ks < 2; ks++) {
            const int kb = ks * 8;
            uint32_t afr[2][4];
            #pragma unroll
            for (int mi = 0; mi < 2; mi++) {
                const int mrow = wm * 32 + mi * 16;
                afr[mi][0] = As[kb + tig    ][mrow + g];
                afr[mi][1] = As[kb + tig    ][mrow + g + 8];
                afr[mi][2] = As[kb + tig + 4][mrow + g];
                afr[mi][3] = As[kb + tig + 4][mrow + g + 8];
            }
            uint32_t bfr[4][2];
            #pragma unroll
            for (int ni = 0; ni < 4; ni++) {
                const int ncol = wn * 32 + ni * 8;
                bfr[ni][0] = Bs[kb + tig    ][ncol + g];
                bfr[ni][1] = Bs[kb + tig + 4][ncol + g];
            }
            #pragma unroll
            for (int mi = 0; mi < 2; mi++)
                #pragma unroll
                for (int ni = 0; ni < 4; ni++)
                    mma_tf32(acc[mi][ni], afr[mi], bfr[ni]);
        }
        __syncthreads();
    }

    // epilogue
    #pragma unroll
    for (int mi = 0; mi < 2; mi++) {
        #pragma unroll
        for (int hi = 0; hi < 2; hi++) {           // c01 (row) / c23 (row+8)
            int r = row0 + wm * 32 + mi * 16 + g + hi * 8;
            if (r >= M) continue;
            #pragma unroll
            for (int ni = 0; ni < 4; ni++) {
                int c = col0 + wn * 32 + ni * 8 + 2 * tig;
                float v0 = acc[mi][ni][hi * 2 + 0] + bias[c];
                float v1 = acc[mi][ni][hi * 2 + 1] + bias[c + 1];
                if (act == 1) {
                    v0 = 0.5f * v0 * (1.0f + erff(v0 * 0.70710678118654752440f));
                    v1 = 0.5f * v1 * (1.0f + erff(v1 * 0.70710678118654752440f));
                }
                if (res) {
                    const float2 rr = *(const float2*)(res + (size_t)r * N + c);
                    v0 += rr.x; v1 += rr.y;
                }
                *(float2*)(C + (size_t)r * N + c) = make_float2(v0, v1);
            }
        }
    }
}

// ---------------- kernel 3: windowed attention, one block per (window, head) ----------------
#define ATTN_SMEM_BYTES ((4608 * 3 + 144 * 145 + 3312) * 4 + 144 * 3 * 4)

__global__ void attn_kernel(const float* __restrict__ bias_table) {
    extern __shared__ float sm[];
    float* Qs = sm;
    float* Ks = Qs + 4608;
    float* Vs = Ks + 4608;
    float* Ss = Vs + 4608;         // stride 145 rows
    float* sB = Ss + 144 * 145;    // 3312
    int*   cM = (int*)(sB + 3312);
    int*   rB = cM + 144;
    int*   rG = rB + 144;

    int blk  = blockIdx.x;
    int g    = blk / HEADS;
    int head = blk % HEADS;
    int ilon = g / NW, iw = g % NW;
    int ipl = iw >> 4, ilat = iw & 15;
    int tid = threadIdx.x;  // 160
    size_t base = (size_t)g * NTOK;
    const float scale = 0.17677669529663687f;  // 1/sqrt(32)

    for (int i = tid; i < 4608; i += 160) {
        int n = i >> 5, d = i & 31;
        size_t o = (base + n) * (3 * DIM) + head * HD + d;
        Qs[i] = g_qkv[o] * scale;
        Ks[i] = g_qkv[o + DIM];
        Vs[i] = g_qkv[o + 2 * DIM];
    }
    for (int i = tid; i < 3312; i += 160)
        sB[i] = bias_table[(size_t)i * (NW * HEADS) + iw * HEADS + head];
    for (int i = tid; i < 144; i += 160) {
        int z = i / 72, h = (i / 12) % 6, w = i % 12;
        cM[i] = 1656 * z + 138 * h - w;
        rB[i] = 828 * z + 23 * h + w + 11;
        int pl = ipl * 2 + z, lat = ilat * 6 + h, lon = ilon * 12 + w;
        rG[i] = (pl < 6 ? 0 : (pl < 7 ? 1 : 2)) * 9
              + (lat < 90 ? 0 : (lat < 93 ? 1 : 2)) * 3
              + (lon < 174 ? 0 : 1);
    }
    __syncthreads();

    if (tid < 144) {
        float q[HD];
        #pragma unroll
        for (int d = 0; d < HD; d++) q[d] = Qs[tid * HD + d];
        int rb = rB[tid], rg = rG[tid];
        float* srow = Ss + tid * 145;
        float mx = -1e30f;
        for (int m = 0; m < 144; m++) {
            const float* kp = Ks + m * HD;
            float s = 0.f;
            #pragma unroll
            for (int d = 0; d < HD; d++) s += q[d] * kp[d];
            s += sB[rb + cM[m]];
            if (rG[m] != rg) s -= 100.0f;
            srow[m] = s;
            mx = fmaxf(mx, s);
        }
        float denom = 0.f;
        for (int m = 0; m < 144; m++) {
            float p = expf(srow[m] - mx);
            srow[m] = p;
            denom += p;
        }
        float inv = 1.0f / denom;
        float out[HD];
        #pragma unroll
        for (int d = 0; d < HD; d++) out[d] = 0.f;
        for (int m = 0; m < 144; m++) {
            float p = srow[m];
            const float* vp = Vs + m * HD;
            #pragma unroll
            for (int d = 0; d < HD; d++) out[d] += p * vp[d];
        }
        size_t o = (base + tid) * DIM + head * HD;
        #pragma unroll
        for (int d = 0; d < HD; d++) g_att[o + d] = out[d] * inv;
    }
}

// ---------------- kernel 5: inverse window scatter + residual + LN2 ----------------
__global__ void resid_ln2_kernel(const float* __restrict__ x,
                                 const float* __restrict__ w2,
                                 const float* __restrict__ b2) {
    int t = blockIdx.x;     // original token 0..LTOK-1
    int c = threadIdx.x;
    int lon = t % 180;
    int lat = (t / 180) % 91;
    int pl  = t / (180 * 91);
    int pl_r  = (pl + 7) & 7;                 // (pl-1) mod 8
    int lat_r = lat - 1; if (lat_r < 0) lat_r += 96;  // (lat+2-3) mod 96
    int lon_r = lon - 6; if (lon_r < 0) lon_r += 180;
    int ilon = lon_r / 12, ww = lon_r % 12;
    int ipl = pl_r >> 1,  z  = pl_r & 1;
    int ilat = lat_r / 6, hh = lat_r % 6;
    size_t wt = (size_t)(ilon * NW + ipl * 16 + ilat) * NTOK + z * 72 + hh * 12 + ww;

    float v = x[(size_t)t * DIM + c] + g_proj[wt * DIM + c];
    g_x1[(size_t)t * DIM + c] = v;
    float mean, var;
    block_meanvar_192(v, mean, var);
    g_h2[(size_t)t * DIM + c] = (v - mean) * rsqrtf(var + EPSLN) * w2[c] + b2[c];
}

// ---------------- launcher ----------------
extern "C" void kernel_launch(void* const* d_in, const int* in_sizes, int n_in,
                              void* d_out, int out_size) {
    const float* x     = (const float*)d_in[0];
    const float* n1w   = (const float*)d_in[1];
    const float* n1b   = (const float*)d_in[2];
    const float* qkvw  = (const float*)d_in[3];
    const float* qkvb  = (const float*)d_in[4];
    const float* btab  = (const float*)d_in[5];
    const float* projw = (const float*)d_in[6];
    const float* projb = (const float*)d_in[7];
    const float* n2w   = (const float*)d_in[8];
    const float* n2b   = (const float*)d_in[9];
    const float* fc1w  = (const float*)d_in[10];
    const float* fc1b  = (const float*)d_in[11];
    const float* fc2w  = (const float*)d_in[12];
    const float* fc2b  = (const float*)d_in[13];
    float* out = (float*)d_out;

    float *p_h, *p_qkv, *p_att, *p_proj, *p_x1, *p_h2, *p_fc1;
    cudaGetSymbolAddress((void**)&p_h,    g_h);
    cudaGetSymbolAddress((void**)&p_qkv,  g_qkv);
    cudaGetSymbolAddress((void**)&p_att,  g_att);
    cudaGetSymbolAddress((void**)&p_proj, g_proj);
    cudaGetSymbolAddress((void**)&p_x1,   g_x1);
    cudaGetSymbolAddress((void**)&p_h2,   g_h2);
    cudaGetSymbolAddress((void**)&p_fc1,  g_fc1);

    cudaFuncSetAttribute(attn_kernel,
                         cudaFuncAttributeMaxDynamicSharedMemorySize,
                         ATTN_SMEM_BYTES);

    // 1. LN1 + window partition
    ln1_window_kernel<<<WTOK, DIM>>>(x, n1w, n1b);

    // 2. QKV gemm: [WTOK,192] x [576,192]^T
    gemm_tf32_kernel<<<dim3(576 / 64, WTOK / 128), 256>>>(
        p_h, qkvw, qkvb, nullptr, p_qkv, WTOK, 3 * DIM, DIM, 0);

    // 3. attention per (window, head)
    attn_kernel<<<NLON * NW * HEADS, 160, ATTN_SMEM_BYTES>>>(btab);

    // 4. proj gemm: [WTOK,192] x [192,192]^T
    gemm_tf32_kernel<<<dim3(DIM / 64, WTOK / 128), 256>>>(
        p_att, projw, projb, nullptr, p_proj, WTOK, DIM, DIM, 0);

    // 5. scatter + residual + LN2
    resid_ln2_kernel<<<LTOK, DIM>>>(x, n2w, n2b);

    // 6. fc1 gemm + exact GELU: [LTOK,192] x [768,192]^T
    gemm_tf32_kernel<<<dim3(HIDDEN / 64, (LTOK + 127) / 128), 256>>>(
        p_h2, fc1w, fc1b, nullptr, p_fc1, LTOK, HIDDEN, DIM, 1);

    // 7. fc2 gemm + residual: [LTOK,768] x [192,768]^T + x1 -> out
    gemm_tf32_kernel<<<dim3(DIM / 64, (LTOK + 127) / 128), 256>>>(
        p_fc1, fc2w, fc2b, p_x1, out, LTOK, DIM, HIDDEN, 0);
}

// round 3
// speedup vs baseline: 2.9795x; 1.9864x over previous
#include <cuda_runtime.h>
#include <cuda_bf16.h>
#include <math.h>
#include <stdint.h>

// ---------------- problem constants ----------------
#define DIM      192
#define HEADS    6
#define HD       32
#define HIDDEN   768
#define NLON     15
#define NW       64
#define NTOK     144
#define WTOK     138240
#define LTOK     131040
#define EPSLN    1e-5f

// ---------------- device scratch ----------------
__device__ __nv_bfloat16 g_h   [(size_t)WTOK * DIM];
__device__ __nv_bfloat16 g_qkv [(size_t)WTOK * 3 * DIM];
__device__ __nv_bfloat16 g_att [(size_t)WTOK * DIM];
__device__ __nv_bfloat16 g_proj[(size_t)WTOK * DIM];
__device__ float         g_x1  [(size_t)LTOK * DIM];
__device__ __nv_bfloat16 g_h2  [(size_t)LTOK * DIM];
__device__ __nv_bfloat16 g_fc1 [(size_t)LTOK * HIDDEN];
__device__ __nv_bfloat16 g_wq  [576 * 192];
__device__ __nv_bfloat16 g_wp  [192 * 192];
__device__ __nv_bfloat16 g_w1  [768 * 192];
__device__ __nv_bfloat16 g_w2  [192 * 768];
__device__ float         g_biasT[(size_t)NW * HEADS * 3312];

// ---------------- small prep kernels ----------------
__global__ void cvt_kernel(const float* __restrict__ a, __nv_bfloat16* __restrict__ b, int n) {
    int i = blockIdx.x * 256 + threadIdx.x;
    if (i < n) b[i] = __float2bfloat16(a[i]);
}

__global__ void biasT_kernel(const float* __restrict__ bt) {
    int i = blockIdx.x;            // 0..3311
    int t = threadIdx.x;           // 0..383 = iw*6+head
    g_biasT[(size_t)t * 3312 + i] = bt[(size_t)i * 384 + t];
}

// ---------------- kernel 1: LN1 + pad + roll + window partition (warp/token) ----------------
__global__ void ln1_window_kernel(const float* __restrict__ x,
                                  const float* __restrict__ w1,
                                  const float* __restrict__ b1) {
    int warp = threadIdx.x >> 5, lane = threadIdx.x & 31;
    int t = blockIdx.x * 8 + warp;               // WTOK/8 blocks exactly
    int ilon = t / (NW * NTOK);
    int rem  = t % (NW * NTOK);
    int iw = rem / NTOK, n = rem % NTOK;
    int ipl = iw >> 4, ilat = iw & 15;
    int z = n / 72, hh = (n / 12) % 6, ww = n % 12;
    int pl_s  = (ipl * 2 + z + 1) & 7;
    int lat_p = ilat * 6 + hh + 3; if (lat_p >= 96) lat_p -= 96;
    int lat_s = lat_p - 2;
    int lon_s = ilon * 12 + ww + 6; if (lon_s >= 180) lon_s -= 180;

    __nv_bfloat16* dst = g_h + (size_t)t * DIM;
    if (lat_s >= 0 && lat_s < 91) {
        const float* src = x + ((size_t)(pl_s * 91 + lat_s) * 180 + lon_s) * DIM;
        float v[6]; float s = 0.f, qq = 0.f;
        #pragma unroll
        for (int j = 0; j < 6; j++) {
            v[j] = src[lane + 32 * j];
            s += v[j]; qq += v[j] * v[j];
        }
        #pragma unroll
        for (int o = 16; o > 0; o >>= 1) {
            s  += __shfl_xor_sync(0xffffffffu, s, o);
            qq += __shfl_xor_sync(0xffffffffu, qq, o);
        }
        float mean = s * (1.f / 192.f);
        float var  = qq * (1.f / 192.f) - mean * mean;
        float rs = rsqrtf(var + EPSLN);
        #pragma unroll
        for (int j = 0; j < 6; j++) {
            int c = lane + 32 * j;
            dst[c] = __float2bfloat16((v[j] - mean) * rs * w1[c] + b1[c]);
        }
    } else {
        #pragma unroll
        for (int j = 0; j < 6; j++) dst[lane + 32 * j] = __float2bfloat16(0.f);
    }
}

// ---------------- bf16 tensor-core GEMM ----------------
// C[M,N] = A[M,K](bf16) * W[N,K](bf16)^T + bias; mode 0: ->bf16; 1: gelu->bf16; 2: +res->fp32
// tile 128x64, BK=32, double-buffered cp.async, 8 warps (4m x 2n), warp tile 32x32
__device__ __forceinline__ uint32_t swz(int row, int kb) {
    int line  = row >> 1;
    int chunk = ((row & 1) << 2) | (kb >> 4);
    int phys  = chunk ^ (line & 7);
    return (uint32_t)(line * 128 + phys * 16 + (kb & 15));
}

__device__ __forceinline__ void cpasync16(uint32_t dst, const void* src, int sz) {
    asm volatile("cp.async.ca.shared.global [%0], [%1], 16, %2;"
                 :: "r"(dst), "l"(src), "r"(sz));
}

__device__ __forceinline__ void ldsm4(uint32_t r[4], uint32_t addr) {
    asm volatile("ldmatrix.sync.aligned.m8n8.x4.shared.b16 {%0,%1,%2,%3}, [%4];"
                 : "=r"(r[0]), "=r"(r[1]), "=r"(r[2]), "=r"(r[3]) : "r"(addr));
}

__device__ __forceinline__ void mma_bf16(float c[4], const uint32_t a[4], const uint32_t b[2]) {
    asm volatile(
        "mma.sync.aligned.m16n8k16.row.col.f32.bf16.bf16.f32 "
        "{%0,%1,%2,%3}, {%4,%5,%6,%7}, {%8,%9}, {%0,%1,%2,%3};"
        : "+f"(c[0]), "+f"(c[1]), "+f"(c[2]), "+f"(c[3])
        : "r"(a[0]), "r"(a[1]), "r"(a[2]), "r"(a[3]), "r"(b[0]), "r"(b[1]));
}

#define ASTAGE 8192
#define BSTAGE 4096
#define STAGE  (ASTAGE + BSTAGE)

__global__ __launch_bounds__(256) void gemm_bf16_kernel(
        const __nv_bfloat16* __restrict__ A,
        const __nv_bfloat16* __restrict__ W,
        const float* __restrict__ bias,
        const float* __restrict__ res,
        __nv_bfloat16* __restrict__ Cb,
        float* __restrict__ Cf,
        int M, int N, int K, int mode) {
    __shared__ __align__(128) uint8_t smem[2 * STAGE];
    uint32_t sbase = (uint32_t)__cvta_generic_to_shared(smem);

    const int tid = threadIdx.x, warp = tid >> 5, lane = tid & 31;
    const int wm = warp & 3, wn = warp >> 2;
    const int g = lane >> 2, tig = lane & 3;
    const int row0 = blockIdx.y * 128;
    const int col0 = blockIdx.x * 64;
    const int nstage = K / 32;

    float acc[2][4][4] = {};

    // fragment ldmatrix addressing (per lane)
    const int quad = lane >> 3;
    const int rr = (quad & 1) * 8 + (lane & 7);
    const int kbq = (quad >> 1) * 16;

    // loader indices
    const int lm = tid >> 2, lc = tid & 3;

    // prologue: stage 0
    {
        uint32_t aB = sbase, bB = sbase + ASTAGE;
        #pragma unroll
        for (int j = 0; j < 2; j++) {
            int m = lm + j * 64;
            const void* src = A + (size_t)(row0 + m) * K + lc * 8;
            cpasync16(aB + swz(m, lc * 16), src, (row0 + m < M) ? 16 : 0);
        }
        cpasync16(bB + swz(lm, lc * 16), W + (size_t)(col0 + lm) * K + lc * 8, 16);
        asm volatile("cp.async.commit_group;");
    }

    for (int s = 0; s < nstage; s++) {
        if (s + 1 < nstage) {
            int k0 = (s + 1) * 32;
            uint32_t aB = sbase + ((s + 1) & 1) * STAGE, bB = aB + ASTAGE;
            #pragma unroll
            for (int j = 0; j < 2; j++) {
                int m = lm + j * 64;
                const void* src = A + (size_t)(row0 + m) * K + k0 + lc * 8;
                cpasync16(aB + swz(m, lc * 16), src, (row0 + m < M) ? 16 : 0);
            }
            cpasync16(bB + swz(lm, lc * 16), W + (size_t)(col0 + lm) * K + k0 + lc * 8, 16);
            asm volatile("cp.async.commit_group;");
            asm volatile("cp.async.wait_group 1;");
        } else {
            asm volatile("cp.async.wait_group 0;");
        }
        __syncthreads();

        uint32_t aB = sbase + (s & 1) * STAGE, bB = aB + ASTAGE;
        #pragma unroll
        for (int ks = 0; ks < 2; ks++) {
            const int kb = ks * 32 + kbq;
            uint32_t afr[2][4], bfr[4][2];
            #pragma unroll
            for (int mi = 0; mi < 2; mi++)
                ldsm4(afr[mi], aB + swz(wm * 32 + mi * 16 + rr, kb));
            #pragma unroll
            for (int np = 0; np < 2; np++) {
                uint32_t r4[4];
                ldsm4(r4, bB + swz(wn * 32 + np * 16 + rr, kb));
                bfr[np * 2 + 0][0] = r4[0]; bfr[np * 2 + 0][1] = r4[2];
                bfr[np * 2 + 1][0] = r4[1]; bfr[np * 2 + 1][1] = r4[3];
            }
            #pragma unroll
            for (int mi = 0; mi < 2; mi++)
                #pragma unroll
                for (int ni = 0; ni < 4; ni++)
                    mma_bf16(acc[mi][ni], afr[mi], bfr[ni]);
        }
        __syncthreads();
    }

    // epilogue
    #pragma unroll
    for (int mi = 0; mi < 2; mi++) {
        #pragma unroll
        for (int hi = 0; hi < 2; hi++) {
            int r = row0 + wm * 32 + mi * 16 + g + hi * 8;
            if (r >= M) continue;
            #pragma unroll
            for (int ni = 0; ni < 4; ni++) {
                int c = col0 + wn * 32 + ni * 8 + 2 * tig;
                float v0 = acc[mi][ni][hi * 2 + 0] + bias[c];
                float v1 = acc[mi][ni][hi * 2 + 1] + bias[c + 1];
                if (mode == 1) {
                    v0 = 0.5f * v0 * (1.0f + erff(v0 * 0.70710678118654752440f));
                    v1 = 0.5f * v1 * (1.0f + erff(v1 * 0.70710678118654752440f));
                }
                if (mode == 2) {
                    const float2 rv = *(const float2*)(res + (size_t)r * N + c);
                    *(float2*)(Cf + (size_t)r * N + c) = make_float2(v0 + rv.x, v1 + rv.y);
                } else {
                    *(__nv_bfloat162*)(Cb + (size_t)r * N + c) = __floats2bfloat162_rn(v0, v1);
                }
            }
        }
    }
}

// ---------------- kernel 3: windowed attention (online softmax) ----------------
#define ATTN_SMEM ((4608 * 2 + 3312) * 4 + 3 * 144 * 4)

__global__ __launch_bounds__(160) void attn_kernel() {
    extern __shared__ float sm[];
    float* Ks = sm;
    float* Vs = Ks + 4608;
    float* sB = Vs + 4608;
    int* cM = (int*)(sB + 3312);
    int* rB = cM + 144;
    int* rG = rB + 144;

    int blk = blockIdx.x;
    int gwin = blk / HEADS, head = blk % HEADS;
    int ilon = gwin / NW, iw = gwin % NW;
    int ipl = iw >> 4, ilat = iw & 15;
    int tid = threadIdx.x;
    size_t base = (size_t)gwin * NTOK;

    for (int i = tid; i < 4608; i += 160) {
        int n = i >> 5, d = i & 31;
        size_t o = (base + n) * (3 * DIM) + head * HD + d;
        Ks[i] = __bfloat162float(g_qkv[o + DIM]);
        Vs[i] = __bfloat162float(g_qkv[o + 2 * DIM]);
    }
    const float* bt = g_biasT + (size_t)(iw * HEADS + head) * 3312;
    for (int i = tid; i < 3312; i += 160) sB[i] = bt[i];
    for (int i = tid; i < 144; i += 160) {
        int z = i / 72, h = (i / 12) % 6, w = i % 12;
        cM[i] = 1656 * z + 138 * h - w;
        rB[i] = 828 * z + 23 * h + w + 11;
        int pl = ipl * 2 + z, lat = ilat * 6 + h, lon = ilon * 12 + w;
        rG[i] = (pl < 6 ? 0 : (pl < 7 ? 1 : 2)) * 9
              + (lat < 90 ? 0 : (lat < 93 ? 1 : 2)) * 3
              + (lon < 174 ? 0 : 1);
    }
    __syncthreads();

    if (tid < 144) {
        float q[HD];
        size_t qo = (base + tid) * (3 * DIM) + head * HD;
        #pragma unroll
        for (int d = 0; d < HD; d++)
            q[d] = __bfloat162float(g_qkv[qo + d]) * 0.17677669529663687f;
        int rb = rB[tid], rg = rG[tid];
        float den = 0.f, out[HD];
        #pragma unroll
        for (int d = 0; d < HD; d++) out[d] = 0.f;
        for (int m = 0; m < 144; m++) {
            const float* kp = Ks + m * HD;
            float s0 = 0.f, s1 = 0.f, s2 = 0.f, s3 = 0.f;
            #pragma unroll
            for (int d = 0; d < HD; d += 4) {
                s0 += q[d] * kp[d];     s1 += q[d + 1] * kp[d + 1];
                s2 += q[d + 2] * kp[d + 2]; s3 += q[d + 3] * kp[d + 3];
            }
            float s = (s0 + s1) + (s2 + s3) + sB[rb + cM[m]];
            if (rG[m] != rg) s -= 100.f;
            float p = __expf(s);
            den += p;
            const float* vp = Vs + m * HD;
            #pragma unroll
            for (int d = 0; d < HD; d++) out[d] += p * vp[d];
        }
        float inv = 1.f / den;
        size_t oo = (base + tid) * DIM + head * HD;
        #pragma unroll
        for (int d = 0; d < HD; d++)
            g_att[oo + d] = __float2bfloat16(out[d] * inv);
    }
}

// ---------------- kernel 5: scatter + residual + LN2 (warp/token) ----------------
__global__ void resid_ln2_kernel(const float* __restrict__ x,
                                 const float* __restrict__ w2,
                                 const float* __restrict__ b2) {
    int warp = threadIdx.x >> 5, lane = threadIdx.x & 31;
    int t = blockIdx.x * 8 + warp;               // LTOK/8 blocks exactly
    int lon = t % 180;
    int lat = (t / 180) % 91;
    int pl  = t / (180 * 91);
    int pl_r  = (pl + 7) & 7;
    int lat_r = lat - 1; if (lat_r < 0) lat_r += 96;
    int lon_r = lon - 6; if (lon_r < 0) lon_r += 180;
    int ilon = lon_r / 12, ww = lon_r % 12;
    int ipl = pl_r >> 1,  z  = pl_r & 1;
    int ilat = lat_r / 6, hh = lat_r % 6;
    size_t wt = (size_t)(ilon * NW + ipl * 16 + ilat) * NTOK + z * 72 + hh * 12 + ww;

    const float* xs = x + (size_t)t * DIM;
    const __nv_bfloat16* ps = g_proj + wt * DIM;
    float v[6]; float s = 0.f, qq = 0.f;
    #pragma unroll
    for (int j = 0; j < 6; j++) {
        int c = lane + 32 * j;
        v[j] = xs[c] + __bfloat162float(ps[c]);
        s += v[j]; qq += v[j] * v[j];
    }
    #pragma unroll
    for (int o = 16; o > 0; o >>= 1) {
        s  += __shfl_xor_sync(0xffffffffu, s, o);
        qq += __shfl_xor_sync(0xffffffffu, qq, o);
    }
    float mean = s * (1.f / 192.f);
    float var  = qq * (1.f / 192.f) - mean * mean;
    float rs = rsqrtf(var + EPSLN);
    #pragma unroll
    for (int j = 0; j < 6; j++) {
        int c = lane + 32 * j;
        g_x1[(size_t)t * DIM + c] = v[j];
        g_h2[(size_t)t * DIM + c] = __float2bfloat16((v[j] - mean) * rs * w2[c] + b2[c]);
    }
}

// ---------------- launcher ----------------
extern "C" void kernel_launch(void* const* d_in, const int* in_sizes, int n_in,
                              void* d_out, int out_size) {
    const float* x     = (const float*)d_in[0];
    const float* n1w   = (const float*)d_in[1];
    const float* n1b   = (const float*)d_in[2];
    const float* qkvw  = (const float*)d_in[3];
    const float* qkvb  = (const float*)d_in[4];
    const float* btab  = (const float*)d_in[5];
    const float* projw = (const float*)d_in[6];
    const float* projb = (const float*)d_in[7];
    const float* n2w   = (const float*)d_in[8];
    const float* n2b   = (const float*)d_in[9];
    const float* fc1w  = (const float*)d_in[10];
    const float* fc1b  = (const float*)d_in[11];
    const float* fc2w  = (const float*)d_in[12];
    const float* fc2b  = (const float*)d_in[13];
    float* out = (float*)d_out;

    __nv_bfloat16 *p_h, *p_qkv, *p_att, *p_proj, *p_h2, *p_fc1;
    __nv_bfloat16 *p_wq, *p_wp, *p_w1, *p_w2;
    float *p_x1;
    cudaGetSymbolAddress((void**)&p_h,    g_h);
    cudaGetSymbolAddress((void**)&p_qkv,  g_qkv);
    cudaGetSymbolAddress((void**)&p_att,  g_att);
    cudaGetSymbolAddress((void**)&p_proj, g_proj);
    cudaGetSymbolAddress((void**)&p_x1,   g_x1);
    cudaGetSymbolAddress((void**)&p_h2,   g_h2);
    cudaGetSymbolAddress((void**)&p_fc1,  g_fc1);
    cudaGetSymbolAddress((void**)&p_wq,   g_wq);
    cudaGetSymbolAddress((void**)&p_wp,   g_wp);
    cudaGetSymbolAddress((void**)&p_w1,   g_w1);
    cudaGetSymbolAddress((void**)&p_w2,   g_w2);

    cudaFuncSetAttribute(attn_kernel,
                         cudaFuncAttributeMaxDynamicSharedMemorySize, ATTN_SMEM);

    // weight conversion + bias transpose
    cvt_kernel<<<(576 * 192 + 255) / 256, 256>>>(qkvw,  p_wq, 576 * 192);
    cvt_kernel<<<(192 * 192 + 255) / 256, 256>>>(projw, p_wp, 192 * 192);
    cvt_kernel<<<(768 * 192 + 255) / 256, 256>>>(fc1w,  p_w1, 768 * 192);
    cvt_kernel<<<(192 * 768 + 255) / 256, 256>>>(fc2w,  p_w2, 192 * 768);
    biasT_kernel<<<3312, 384>>>(btab);

    // 1. LN1 + window partition
    ln1_window_kernel<<<WTOK / 8, 256>>>(x, n1w, n1b);

    // 2. QKV gemm
    gemm_bf16_kernel<<<dim3(9, WTOK / 128), 256>>>(
        p_h, p_wq, qkvb, nullptr, p_qkv, nullptr, WTOK, 576, 192, 0);

    // 3. attention
    attn_kernel<<<NLON * NW * HEADS, 160, ATTN_SMEM>>>();

    // 4. proj gemm
    gemm_bf16_kernel<<<dim3(3, WTOK / 128), 256>>>(
        p_att, p_wp, projb, nullptr, p_proj, nullptr, WTOK, 192, 192, 0);

    // 5. scatter + residual + LN2
    resid_ln2_kernel<<<LTOK / 8, 256>>>(x, n2w, n2b);

    // 6. fc1 gemm + gelu
    gemm_bf16_kernel<<<dim3(12, (LTOK + 127) / 128), 256>>>(
        p_h2, p_w1, fc1b, nullptr, p_fc1, nullptr, LTOK, 768, 192, 1);

    // 7. fc2 gemm + residual -> out
    gemm_bf16_kernel<<<dim3(3, (LTOK + 127) / 128), 256>>>(
        p_fc1, p_w2, fc2b, p_x1, nullptr, out, LTOK, 192, 768, 2);
}

// round 5
// speedup vs baseline: 4.5329x; 1.5214x over previous
#include <cuda_runtime.h>
#include <cuda_bf16.h>
#include <math.h>
#include <stdint.h>

// ---------------- problem constants ----------------
#define DIM      192
#define HEADS    6
#define HD       32
#define HIDDEN   768
#define NLON     15
#define NW       64
#define NTOK     144
#define WTOK     138240
#define LTOK     131040
#define EPSLN    1e-5f
#define QKSCALE  0.17677669529663687f

// ---------------- device scratch ----------------
__device__ __nv_bfloat16 g_h   [(size_t)WTOK * DIM];
__device__ __nv_bfloat16 g_qkv [(size_t)WTOK * 3 * DIM];
__device__ __nv_bfloat16 g_att [(size_t)WTOK * DIM];
__device__ __nv_bfloat16 g_proj[(size_t)WTOK * DIM];
__device__ float         g_x1  [(size_t)LTOK * DIM];
__device__ __nv_bfloat16 g_h2  [(size_t)LTOK * DIM];
__device__ __nv_bfloat16 g_fc1 [(size_t)LTOK * HIDDEN];
__device__ __nv_bfloat16 g_wq  [576 * 192];
__device__ __nv_bfloat16 g_wp  [192 * 192];
__device__ __nv_bfloat16 g_w1  [768 * 192];
__device__ __nv_bfloat16 g_w2  [192 * 768];
__device__ float         g_biasT[(size_t)NW * HEADS * 3312];
__device__ __nv_bfloat16 g_bmask[(size_t)2 * NW * HEADS * NTOK * NTOK];  // 31.8 MB

// ---------------- small prep kernels ----------------
__global__ void cvt_kernel(const float* __restrict__ a, __nv_bfloat16* __restrict__ b, int n) {
    int i = blockIdx.x * 256 + threadIdx.x;
    if (i < n) b[i] = __float2bfloat16(a[i]);
}

__global__ void biasT_kernel(const float* __restrict__ bt) {
    int i = blockIdx.x;            // 0..3311
    int t = threadIdx.x;           // 0..383 = iw*6+head
    g_biasT[(size_t)t * 3312 + i] = bt[(size_t)i * 384 + t];
}

// combined (bias + shift-mask) matrices: [cls][iw][head][144][144] bf16
__global__ void bmask_kernel() {
    __shared__ float tb[3312];
    __shared__ int rb[144], cm[144], rg[144];
    int b = blockIdx.x;                 // cls*384 + iw*6 + head
    int cls = b / 384, rem = b % 384;
    int iw = rem / 6;
    int ipl = iw >> 4, ilat = iw & 15;
    int tid = threadIdx.x;
    const float* src = g_biasT + (size_t)rem * 3312;
    for (int i = tid; i < 3312; i += 256) tb[i] = src[i];
    for (int i = tid; i < 144; i += 256) {
        int z = i / 72, h = (i / 12) % 6, w = i % 12;
        cm[i] = 1656 * z + 138 * h - w;
        rb[i] = 828 * z + 23 * h + w + 11;
        int pl = ipl * 2 + z, lat = ilat * 6 + h;
        int lonr = cls ? (w < 6 ? 0 : 1) : 0;   // ilon=14 -> lon=168+w
        rg[i] = (pl < 6 ? 0 : (pl < 7 ? 1 : 2)) * 9
              + (lat < 90 ? 0 : (lat < 93 ? 1 : 2)) * 3 + lonr;
    }
    __syncthreads();
    __nv_bfloat16* dst = g_bmask + (size_t)b * (NTOK * NTOK);
    for (int e = tid; e < NTOK * NTOK; e += 256) {
        int r = e / 144, c = e - r * 144;
        float v = tb[rb[r] + cm[c]];
        if (rg[r] != rg[c]) v -= 100.f;
        dst[e] = __float2bfloat16(v);
    }
}

// ---------------- kernel 1: LN1 + pad + roll + window partition ----------------
__global__ void ln1_window_kernel(const float* __restrict__ x,
                                  const float* __restrict__ w1,
                                  const float* __restrict__ b1) {
    int warp = threadIdx.x >> 5, lane = threadIdx.x & 31;
    int t = blockIdx.x * 8 + warp;
    int ilon = t / (NW * NTOK);
    int rem  = t % (NW * NTOK);
    int iw = rem / NTOK, n = rem % NTOK;
    int ipl = iw >> 4, ilat = iw & 15;
    int z = n / 72, hh = (n / 12) % 6, ww = n % 12;
    int pl_s  = (ipl * 2 + z + 1) & 7;
    int lat_p = ilat * 6 + hh + 3; if (lat_p >= 96) lat_p -= 96;
    int lat_s = lat_p - 2;
    int lon_s = ilon * 12 + ww + 6; if (lon_s >= 180) lon_s -= 180;

    __nv_bfloat16* dst = g_h + (size_t)t * DIM;
    if (lat_s >= 0 && lat_s < 91) {
        const float* src = x + ((size_t)(pl_s * 91 + lat_s) * 180 + lon_s) * DIM;
        float v[6]; float s = 0.f, qq = 0.f;
        #pragma unroll
        for (int j = 0; j < 6; j++) {
            v[j] = src[lane + 32 * j];
            s += v[j]; qq += v[j] * v[j];
        }
        #pragma unroll
        for (int o = 16; o > 0; o >>= 1) {
            s  += __shfl_xor_sync(0xffffffffu, s, o);
            qq += __shfl_xor_sync(0xffffffffu, qq, o);
        }
        float mean = s * (1.f / 192.f);
        float var  = qq * (1.f / 192.f) - mean * mean;
        float rs = rsqrtf(var + EPSLN);
        #pragma unroll
        for (int j = 0; j < 6; j++) {
            int c = lane + 32 * j;
            dst[c] = __float2bfloat16((v[j] - mean) * rs * w1[c] + b1[c]);
        }
    } else {
        #pragma unroll
        for (int j = 0; j < 6; j++) dst[lane + 32 * j] = __float2bfloat16(0.f);
    }
}

// ---------------- shared MMA helpers ----------------
__device__ __forceinline__ void ldsm4(uint32_t r[4], uint32_t addr) {
    asm volatile("ldmatrix.sync.aligned.m8n8.x4.shared.b16 {%0,%1,%2,%3}, [%4];"
                 : "=r"(r[0]), "=r"(r[1]), "=r"(r[2]), "=r"(r[3]) : "r"(addr));
}
__device__ __forceinline__ void ldsm4t(uint32_t r[4], uint32_t addr) {
    asm volatile("ldmatrix.sync.aligned.m8n8.x4.trans.shared.b16 {%0,%1,%2,%3}, [%4];"
                 : "=r"(r[0]), "=r"(r[1]), "=r"(r[2]), "=r"(r[3]) : "r"(addr));
}
__device__ __forceinline__ void mma_bf16(float c[4], const uint32_t a[4],
                                         uint32_t b0, uint32_t b1) {
    asm volatile(
        "mma.sync.aligned.m16n8k16.row.col.f32.bf16.bf16.f32 "
        "{%0,%1,%2,%3}, {%4,%5,%6,%7}, {%8,%9}, {%0,%1,%2,%3};"
        : "+f"(c[0]), "+f"(c[1]), "+f"(c[2]), "+f"(c[3])
        : "r"(a[0]), "r"(a[1]), "r"(a[2]), "r"(a[3]), "r"(b0), "r"(b1));
}

__device__ __forceinline__ uint32_t pack_bf2(float a, float b) {
    __nv_bfloat162 t = __floats2bfloat162_rn(a, b);
    uint32_t u;
    memcpy(&u, &t, 4);
    return u;
}

// ---------------- bf16 tensor-core GEMM (unchanged from R3) ----------------
__device__ __forceinline__ uint32_t swz(int row, int kb) {
    int line  = row >> 1;
    int chunk = ((row & 1) << 2) | (kb >> 4);
    int phys  = chunk ^ (line & 7);
    return (uint32_t)(line * 128 + phys * 16 + (kb & 15));
}
__device__ __forceinline__ void cpasync16(uint32_t dst, const void* src, int sz) {
    asm volatile("cp.async.ca.shared.global [%0], [%1], 16, %2;"
                 :: "r"(dst), "l"(src), "r"(sz));
}

#define ASTAGE 8192
#define BSTAGE 4096
#define STAGE  (ASTAGE + BSTAGE)

__global__ __launch_bounds__(256) void gemm_bf16_kernel(
        const __nv_bfloat16* __restrict__ A,
        const __nv_bfloat16* __restrict__ W,
        const float* __restrict__ bias,
        const float* __restrict__ res,
        __nv_bfloat16* __restrict__ Cb,
        float* __restrict__ Cf,
        int M, int N, int K, int mode) {
    __shared__ __align__(128) uint8_t smem[2 * STAGE];
    uint32_t sbase = (uint32_t)__cvta_generic_to_shared(smem);

    const int tid = threadIdx.x, warp = tid >> 5, lane = tid & 31;
    const int wm = warp & 3, wn = warp >> 2;
    const int g = lane >> 2, tig = lane & 3;
    const int row0 = blockIdx.y * 128;
    const int col0 = blockIdx.x * 64;
    const int nstage = K / 32;

    float acc[2][4][4] = {};
    const int quad = lane >> 3;
    const int rr = (quad & 1) * 8 + (lane & 7);
    const int kbq = (quad >> 1) * 16;
    const int lm = tid >> 2, lc = tid & 3;

    {
        uint32_t aB = sbase, bB = sbase + ASTAGE;
        #pragma unroll
        for (int j = 0; j < 2; j++) {
            int m = lm + j * 64;
            const void* src = A + (size_t)(row0 + m) * K + lc * 8;
            cpasync16(aB + swz(m, lc * 16), src, (row0 + m < M) ? 16 : 0);
        }
        cpasync16(bB + swz(lm, lc * 16), W + (size_t)(col0 + lm) * K + lc * 8, 16);
        asm volatile("cp.async.commit_group;");
    }

    for (int s = 0; s < nstage; s++) {
        if (s + 1 < nstage) {
            int k0 = (s + 1) * 32;
            uint32_t aB = sbase + ((s + 1) & 1) * STAGE, bB = aB + ASTAGE;
            #pragma unroll
            for (int j = 0; j < 2; j++) {
                int m = lm + j * 64;
                const void* src = A + (size_t)(row0 + m) * K + k0 + lc * 8;
                cpasync16(aB + swz(m, lc * 16), src, (row0 + m < M) ? 16 : 0);
            }
            cpasync16(bB + swz(lm, lc * 16), W + (size_t)(col0 + lm) * K + k0 + lc * 8, 16);
            asm volatile("cp.async.commit_group;");
            asm volatile("cp.async.wait_group 1;");
        } else {
            asm volatile("cp.async.wait_group 0;");
        }
        __syncthreads();

        uint32_t aB = sbase + (s & 1) * STAGE, bB = aB + ASTAGE;
        #pragma unroll
        for (int ks = 0; ks < 2; ks++) {
            const int kb = ks * 32 + kbq;
            uint32_t afr[2][4], bfr[4][2];
            #pragma unroll
            for (int mi = 0; mi < 2; mi++)
                ldsm4(afr[mi], aB + swz(wm * 32 + mi * 16 + rr, kb));
            #pragma unroll
            for (int np = 0; np < 2; np++) {
                uint32_t r4[4];
                ldsm4(r4, bB + swz(wn * 32 + np * 16 + rr, kb));
                bfr[np * 2 + 0][0] = r4[0]; bfr[np * 2 + 0][1] = r4[2];
                bfr[np * 2 + 1][0] = r4[1]; bfr[np * 2 + 1][1] = r4[3];
            }
            #pragma unroll
            for (int mi = 0; mi < 2; mi++)
                #pragma unroll
                for (int ni = 0; ni < 4; ni++)
                    mma_bf16(acc[mi][ni], afr[mi], bfr[ni][0], bfr[ni][1]);
        }
        __syncthreads();
    }

    #pragma unroll
    for (int mi = 0; mi < 2; mi++) {
        #pragma unroll
        for (int hi = 0; hi < 2; hi++) {
            int r = row0 + wm * 32 + mi * 16 + g + hi * 8;
            if (r >= M) continue;
            #pragma unroll
            for (int ni = 0; ni < 4; ni++) {
                int c = col0 + wn * 32 + ni * 8 + 2 * tig;
                float v0 = acc[mi][ni][hi * 2 + 0] + bias[c];
                float v1 = acc[mi][ni][hi * 2 + 1] + bias[c + 1];
                if (mode == 1) {
                    v0 = 0.5f * v0 * (1.0f + erff(v0 * 0.70710678118654752440f));
                    v1 = 0.5f * v1 * (1.0f + erff(v1 * 0.70710678118654752440f));
                }
                if (mode == 2) {
                    const float2 rv = *(const float2*)(res + (size_t)r * N + c);
                    *(float2*)(Cf + (size_t)r * N + c) = make_float2(v0 + rv.x, v1 + rv.y);
                } else {
                    *(__nv_bfloat162*)(Cb + (size_t)r * N + c) = __floats2bfloat162_rn(v0, v1);
                }
            }
        }
    }
}

// ---------------- kernel 3: tensor-core windowed attention ----------------
// block = (window, head), 288 threads = 9 warps, warp = 16 rows.
// smem: Q/K/V [144][32] bf16, 64B rows, 16B-chunk XOR swizzle (chunk ^ ((row>>1)&3)).
__device__ __forceinline__ uint32_t swa(uint32_t base, int row, int chunk) {
    return base + row * 64 + ((chunk ^ ((row >> 1) & 3)) << 4);
}

__global__ __launch_bounds__(288, 2) void attn_kernel() {
    __shared__ __align__(128) __nv_bfloat16 sQ[144 * 32];
    __shared__ __align__(128) __nv_bfloat16 sK[144 * 32];
    __shared__ __align__(128) __nv_bfloat16 sV[144 * 32];

    const int blk = blockIdx.x;
    const int gwin = blk / HEADS, head = blk % HEADS;
    const int ilon = gwin / NW, iw = gwin % NW;
    const int tid = threadIdx.x;
    const size_t base = (size_t)gwin * NTOK;

    // stage Q/K/V for this head
    {
        const __nv_bfloat16* tb = g_qkv + base * 576 + head * 32;
        for (int i = tid; i < 576; i += 288) {
            int n = i >> 2, c = i & 3;
            int off = n * 32 + ((c ^ ((n >> 1) & 3)) << 3);
            const __nv_bfloat16* tp = tb + (size_t)n * 576 + c * 8;
            *(uint4*)(sQ + off) = *(const uint4*)(tp);
            *(uint4*)(sK + off) = *(const uint4*)(tp + 192);
            *(uint4*)(sV + off) = *(const uint4*)(tp + 384);
        }
    }
    __syncthreads();

    const uint32_t qB = (uint32_t)__cvta_generic_to_shared(sQ);
    const uint32_t kB = (uint32_t)__cvta_generic_to_shared(sK);
    const uint32_t vB = (uint32_t)__cvta_generic_to_shared(sV);

    const int warp = tid >> 5, lane = tid & 31;
    const int g = lane >> 2, tig = lane & 3;
    const int m0 = warp * 16;

    // Q fragments (16 x 32)
    uint32_t aq[2][4];
    #pragma unroll
    for (int kq = 0; kq < 2; kq++)
        ldsm4(aq[kq], swa(qB, m0 + (lane & 15), kq * 2 + (lane >> 4)));

    const __nv_bfloat16* bm = g_bmask
        + ((size_t)((ilon == 14 ? 1 : 0) * 384 + iw * HEADS + head)) * (NTOK * NTOK);
    const int r0 = m0 + g, r1 = r0 + 8;

    float den0 = 0.f, den1 = 0.f;
    float o[4][4] = {};

    // two column passes: nt 0..9 (kc 0..4), nt 10..17 (kc 5..8)
    #pragma unroll
    for (int ph = 0; ph < 2; ph++) {
        const int ntS = ph ? 10 : 0, ntE = ph ? 18 : 10;
        const int kcS = ph ? 5 : 0,  kcE = ph ? 9 : 5;

        float acc[10][4];
        #pragma unroll
        for (int j = 0; j < 10; j++)
            #pragma unroll
            for (int q = 0; q < 4; q++) acc[j][q] = 0.f;

        for (int nt = ntS; nt < ntE; nt++) {
            uint32_t bk[4];
            ldsm4(bk, swa(kB, nt * 8 + (lane & 7), lane >> 3));
            mma_bf16(acc[nt - ntS], aq[0], bk[0], bk[1]);
            mma_bf16(acc[nt - ntS], aq[1], bk[2], bk[3]);
        }

        uint32_t paLo[10], paHi[10];
        for (int nt = ntS; nt < ntE; nt++) {
            int j = nt - ntS;
            int c0 = nt * 8 + 2 * tig;
            __nv_bfloat162 b0 = *(const __nv_bfloat162*)(bm + (size_t)r0 * 144 + c0);
            __nv_bfloat162 b1 = *(const __nv_bfloat162*)(bm + (size_t)r1 * 144 + c0);
            float p0 = __expf(fmaf(acc[j][0], QKSCALE, __bfloat162float(b0.x)));
            float p1 = __expf(fmaf(acc[j][1], QKSCALE, __bfloat162float(b0.y)));
            float p2 = __expf(fmaf(acc[j][2], QKSCALE, __bfloat162float(b1.x)));
            float p3 = __expf(fmaf(acc[j][3], QKSCALE, __bfloat162float(b1.y)));
            den0 += p0 + p1; den1 += p2 + p3;
            paLo[j] = pack_bf2(p0, p1);
            paHi[j] = pack_bf2(p2, p3);
        }

        for (int kc = kcS; kc < kcE; kc++) {
            int j2 = 2 * (kc - kcS);
            uint32_t A[4] = {paLo[j2], paHi[j2], paLo[j2 + 1], paHi[j2 + 1]};
            #pragma unroll
            for (int np = 0; np < 2; np++) {
                uint32_t bv[4];
                ldsm4t(bv, swa(vB, kc * 16 + ((lane >> 3) & 1) * 8 + (lane & 7),
                               np * 2 + (lane >> 4)));
                mma_bf16(o[np * 2 + 0], A, bv[0], bv[1]);
                mma_bf16(o[np * 2 + 1], A, bv[2], bv[3]);
            }
        }
    }

    // reduce denominators across the 4 lanes of each row group
    den0 += __shfl_xor_sync(0xffffffffu, den0, 1);
    den0 += __shfl_xor_sync(0xffffffffu, den0, 2);
    den1 += __shfl_xor_sync(0xffffffffu, den1, 1);
    den1 += __shfl_xor_sync(0xffffffffu, den1, 2);
    float inv0 = 1.f / den0, inv1 = 1.f / den1;

    __nv_bfloat16* ob = g_att + base * DIM + head * HD;
    #pragma unroll
    for (int nt4 = 0; nt4 < 4; nt4++) {
        int col = nt4 * 8 + 2 * tig;
        *(__nv_bfloat162*)(ob + (size_t)r0 * DIM + col) =
            __floats2bfloat162_rn(o[nt4][0] * inv0, o[nt4][1] * inv0);
        *(__nv_bfloat162*)(ob + (size_t)r1 * DIM + col) =
            __floats2bfloat162_rn(o[nt4][2] * inv1, o[nt4][3] * inv1);
    }
}

// ---------------- kernel 5: scatter + residual + LN2 ----------------
__global__ void resid_ln2_kernel(const float* __restrict__ x,
                                 const float* __restrict__ w2,
                                 const float* __restrict__ b2) {
    int warp = threadIdx.x >> 5, lane = threadIdx.x & 31;
    int t = blockIdx.x * 8 + warp;
    int lon = t % 180;
    int lat = (t / 180) % 91;
    int pl  = t / (180 * 91);
    int pl_r  = (pl + 7) & 7;
    int lat_r = lat - 1; if (lat_r < 0) lat_r += 96;
    int lon_r = lon - 6; if (lon_r < 0) lon_r += 180;
    int ilon = lon_r / 12, ww = lon_r % 12;
    int ipl = pl_r >> 1,  z  = pl_r & 1;
    int ilat = lat_r / 6, hh = lat_r % 6;
    size_t wt = (size_t)(ilon * NW + ipl * 16 + ilat) * NTOK + z * 72 + hh * 12 + ww;

    const float* xs = x + (size_t)t * DIM;
    const __nv_bfloat16* ps = g_proj + wt * DIM;
    float v[6]; float s = 0.f, qq = 0.f;
    #pragma unroll
    for (int j = 0; j < 6; j++) {
        int c = lane + 32 * j;
        v[j] = xs[c] + __bfloat162float(ps[c]);
        s += v[j]; qq += v[j] * v[j];
    }
    #pragma unroll
    for (int o = 16; o > 0; o >>= 1) {
        s  += __shfl_xor_sync(0xffffffffu, s, o);
        qq += __shfl_xor_sync(0xffffffffu, qq, o);
    }
    float mean = s * (1.f / 192.f);
    float var  = qq * (1.f / 192.f) - mean * mean;
    float rs = rsqrtf(var + EPSLN);
    #pragma unroll
    for (int j = 0; j < 6; j++) {
        int c = lane + 32 * j;
        g_x1[(size_t)t * DIM + c] = v[j];
        g_h2[(size_t)t * DIM + c] = __float2bfloat16((v[j] - mean) * rs * w2[c] + b2[c]);
    }
}

// ---------------- launcher ----------------
extern "C" void kernel_launch(void* const* d_in, const int* in_sizes, int n_in,
                              void* d_out, int out_size) {
    const float* x     = (const float*)d_in[0];
    const float* n1w   = (const float*)d_in[1];
    const float* n1b   = (const float*)d_in[2];
    const float* qkvw  = (const float*)d_in[3];
    const float* qkvb  = (const float*)d_in[4];
    const float* btab  = (const float*)d_in[5];
    const float* projw = (const float*)d_in[6];
    const float* projb = (const float*)d_in[7];
    const float* n2w   = (const float*)d_in[8];
    const float* n2b   = (const float*)d_in[9];
    const float* fc1w  = (const float*)d_in[10];
    const float* fc1b  = (const float*)d_in[11];
    const float* fc2w  = (const float*)d_in[12];
    const float* fc2b  = (const float*)d_in[13];
    float* out = (float*)d_out;

    __nv_bfloat16 *p_h, *p_qkv, *p_att, *p_proj, *p_h2, *p_fc1;
    __nv_bfloat16 *p_wq, *p_wp, *p_w1, *p_w2;
    float *p_x1;
    cudaGetSymbolAddress((void**)&p_h,    g_h);
    cudaGetSymbolAddress((void**)&p_qkv,  g_qkv);
    cudaGetSymbolAddress((void**)&p_att,  g_att);
    cudaGetSymbolAddress((void**)&p_proj, g_proj);
    cudaGetSymbolAddress((void**)&p_x1,   g_x1);
    cudaGetSymbolAddress((void**)&p_h2,   g_h2);
    cudaGetSymbolAddress((void**)&p_fc1,  g_fc1);
    cudaGetSymbolAddress((void**)&p_wq,   g_wq);
    cudaGetSymbolAddress((void**)&p_wp,   g_wp);
    cudaGetSymbolAddress((void**)&p_w1,   g_w1);
    cudaGetSymbolAddress((void**)&p_w2,   g_w2);

    // weight conversion + bias transpose + combined bias/mask matrices
    cvt_kernel<<<(576 * 192 + 255) / 256, 256>>>(qkvw,  p_wq, 576 * 192);
    cvt_kernel<<<(192 * 192 + 255) / 256, 256>>>(projw, p_wp, 192 * 192);
    cvt_kernel<<<(768 * 192 + 255) / 256, 256>>>(fc1w,  p_w1, 768 * 192);
    cvt_kernel<<<(192 * 768 + 255) / 256, 256>>>(fc2w,  p_w2, 192 * 768);
    biasT_kernel<<<3312, 384>>>(btab);
    bmask_kernel<<<768, 256>>>();

    // 1. LN1 + window partition
    ln1_window_kernel<<<WTOK / 8, 256>>>(x, n1w, n1b);

    // 2. QKV gemm
    gemm_bf16_kernel<<<dim3(9, WTOK / 128), 256>>>(
        p_h, p_wq, qkvb, nullptr, p_qkv, nullptr, WTOK, 576, 192, 0);

    // 3. attention
    attn_kernel<<<NLON * NW * HEADS, 288>>>();

    // 4. proj gemm
    gemm_bf16_kernel<<<dim3(3, WTOK / 128), 256>>>(
        p_att, p_wp, projb, nullptr, p_proj, nullptr, WTOK, 192, 192, 0);

    // 5. scatter + residual + LN2
    resid_ln2_kernel<<<LTOK / 8, 256>>>(x, n2w, n2b);

    // 6. fc1 gemm + gelu
    gemm_bf16_kernel<<<dim3(12, (LTOK + 127) / 128), 256>>>(
        p_h2, p_w1, fc1b, nullptr, p_fc1, nullptr, LTOK, 768, 192, 1);

    // 7. fc2 gemm + residual -> out
    gemm_bf16_kernel<<<dim3(3, (LTOK + 127) / 128), 256>>>(
        p_fc1, p_w2, fc2b, p_x1, nullptr, out, LTOK, 192, 768, 2);
}

// round 6
// speedup vs baseline: 4.8601x; 1.0722x over previous
#include <cuda_runtime.h>
#include <cuda_bf16.h>
#include <math.h>
#include <stdint.h>

// ---------------- problem constants ----------------
#define DIM      192
#define HEADS    6
#define HD       32
#define HIDDEN   768
#define NLON     15
#define NW       64
#define NTOK     144
#define WTOK     138240
#define LTOK     131040
#define EPSLN    1e-5f
#define QKSCALE  0.17677669529663687f

// ---------------- device scratch ----------------
__device__ __nv_bfloat16 g_h   [(size_t)WTOK * DIM];
__device__ __nv_bfloat16 g_qkv [(size_t)WTOK * 3 * DIM];
__device__ __nv_bfloat16 g_att [(size_t)WTOK * DIM];
__device__ __nv_bfloat16 g_proj[(size_t)WTOK * DIM];
__device__ float         g_x1  [(size_t)LTOK * DIM];
__device__ __nv_bfloat16 g_h2  [(size_t)LTOK * DIM];
__device__ __nv_bfloat16 g_fc1 [(size_t)LTOK * HIDDEN];
__device__ __nv_bfloat16 g_wq  [576 * 192];
__device__ __nv_bfloat16 g_wp  [192 * 192];
__device__ __nv_bfloat16 g_w1  [768 * 192];
__device__ __nv_bfloat16 g_w2  [192 * 768];
__device__ float         g_biasT[(size_t)NW * HEADS * 3312];
__device__ __nv_bfloat16 g_bmask[(size_t)2 * NW * HEADS * NTOK * NTOK];  // 31.8 MB

// ---------------- small prep kernels ----------------
__global__ void cvt_kernel(const float* __restrict__ a, __nv_bfloat16* __restrict__ b, int n) {
    int i = blockIdx.x * 256 + threadIdx.x;
    if (i < n) b[i] = __float2bfloat16(a[i]);
}

__global__ void biasT_kernel(const float* __restrict__ bt) {
    int i = blockIdx.x;            // 0..3311
    int t = threadIdx.x;           // 0..383 = iw*6+head
    g_biasT[(size_t)t * 3312 + i] = bt[(size_t)i * 384 + t];
}

// combined (bias + shift-mask) matrices: [cls][iw][head][144][144] bf16
__global__ void bmask_kernel() {
    __shared__ float tb[3312];
    __shared__ int rb[144], cm[144], rg[144];
    int b = blockIdx.x;                 // cls*384 + iw*6 + head
    int cls = b / 384, rem = b % 384;
    int iw = rem / 6;
    int ipl = iw >> 4, ilat = iw & 15;
    int tid = threadIdx.x;
    const float* src = g_biasT + (size_t)rem * 3312;
    for (int i = tid; i < 3312; i += 256) tb[i] = src[i];
    for (int i = tid; i < 144; i += 256) {
        int z = i / 72, h = (i / 12) % 6, w = i % 12;
        cm[i] = 1656 * z + 138 * h - w;
        rb[i] = 828 * z + 23 * h + w + 11;
        int pl = ipl * 2 + z, lat = ilat * 6 + h;
        int lonr = cls ? (w < 6 ? 0 : 1) : 0;   // ilon=14 -> lon=168+w
        rg[i] = (pl < 6 ? 0 : (pl < 7 ? 1 : 2)) * 9
              + (lat < 90 ? 0 : (lat < 93 ? 1 : 2)) * 3 + lonr;
    }
    __syncthreads();
    __nv_bfloat16* dst = g_bmask + (size_t)b * (NTOK * NTOK);
    for (int e = tid; e < NTOK * NTOK; e += 256) {
        int r = e / 144, c = e - r * 144;
        float v = tb[rb[r] + cm[c]];
        if (rg[r] != rg[c]) v -= 100.f;
        dst[e] = __float2bfloat16(v);
    }
}

// ---------------- kernel 1: LN1 + pad + roll + window partition ----------------
__global__ void ln1_window_kernel(const float* __restrict__ x,
                                  const float* __restrict__ w1,
                                  const float* __restrict__ b1) {
    int warp = threadIdx.x >> 5, lane = threadIdx.x & 31;
    int t = blockIdx.x * 8 + warp;
    int ilon = t / (NW * NTOK);
    int rem  = t % (NW * NTOK);
    int iw = rem / NTOK, n = rem % NTOK;
    int ipl = iw >> 4, ilat = iw & 15;
    int z = n / 72, hh = (n / 12) % 6, ww = n % 12;
    int pl_s  = (ipl * 2 + z + 1) & 7;
    int lat_p = ilat * 6 + hh + 3; if (lat_p >= 96) lat_p -= 96;
    int lat_s = lat_p - 2;
    int lon_s = ilon * 12 + ww + 6; if (lon_s >= 180) lon_s -= 180;

    __nv_bfloat16* dst = g_h + (size_t)t * DIM;
    if (lat_s >= 0 && lat_s < 91) {
        const float* src = x + ((size_t)(pl_s * 91 + lat_s) * 180 + lon_s) * DIM;
        float v[6]; float s = 0.f, qq = 0.f;
        #pragma unroll
        for (int j = 0; j < 6; j++) {
            v[j] = src[lane + 32 * j];
            s += v[j]; qq += v[j] * v[j];
        }
        #pragma unroll
        for (int o = 16; o > 0; o >>= 1) {
            s  += __shfl_xor_sync(0xffffffffu, s, o);
            qq += __shfl_xor_sync(0xffffffffu, qq, o);
        }
        float mean = s * (1.f / 192.f);
        float var  = qq * (1.f / 192.f) - mean * mean;
        float rs = rsqrtf(var + EPSLN);
        #pragma unroll
        for (int j = 0; j < 6; j++) {
            int c = lane + 32 * j;
            dst[c] = __float2bfloat16((v[j] - mean) * rs * w1[c] + b1[c]);
        }
    } else {
        #pragma unroll
        for (int j = 0; j < 6; j++) dst[lane + 32 * j] = __float2bfloat16(0.f);
    }
}

// ---------------- shared MMA helpers ----------------
__device__ __forceinline__ void ldsm4(uint32_t r[4], uint32_t addr) {
    asm volatile("ldmatrix.sync.aligned.m8n8.x4.shared.b16 {%0,%1,%2,%3}, [%4];"
                 : "=r"(r[0]), "=r"(r[1]), "=r"(r[2]), "=r"(r[3]) : "r"(addr));
}
__device__ __forceinline__ void ldsm4t(uint32_t r[4], uint32_t addr) {
    asm volatile("ldmatrix.sync.aligned.m8n8.x4.trans.shared.b16 {%0,%1,%2,%3}, [%4];"
                 : "=r"(r[0]), "=r"(r[1]), "=r"(r[2]), "=r"(r[3]) : "r"(addr));
}
__device__ __forceinline__ void mma_bf16(float c[4], const uint32_t a[4],
                                         uint32_t b0, uint32_t b1) {
    asm volatile(
        "mma.sync.aligned.m16n8k16.row.col.f32.bf16.bf16.f32 "
        "{%0,%1,%2,%3}, {%4,%5,%6,%7}, {%8,%9}, {%0,%1,%2,%3};"
        : "+f"(c[0]), "+f"(c[1]), "+f"(c[2]), "+f"(c[3])
        : "r"(a[0]), "r"(a[1]), "r"(a[2]), "r"(a[3]), "r"(b0), "r"(b1));
}

__device__ __forceinline__ uint32_t pack_bf2(float a, float b) {
    __nv_bfloat162 t = __floats2bfloat162_rn(a, b);
    uint32_t u;
    memcpy(&u, &t, 4);
    return u;
}

// ---------------- bf16 tensor-core GEMM ----------------
// C[M,N] = A[M,K](bf16) * W[N,K](bf16)^T + bias; mode 0: ->bf16; 1: gelu->bf16; 2: +res->fp32
// tile 256x64, BK=32, double-buffered cp.async, 8 warps (4m x 2n), warp tile 64x32
__device__ __forceinline__ uint32_t swz(int row, int kb) {
    int line  = row >> 1;
    int chunk = ((row & 1) << 2) | (kb >> 4);
    int phys  = chunk ^ (line & 7);
    return (uint32_t)(line * 128 + phys * 16 + (kb & 15));
}
__device__ __forceinline__ void cpasync16(uint32_t dst, const void* src, int sz) {
    asm volatile("cp.async.ca.shared.global [%0], [%1], 16, %2;"
                 :: "r"(dst), "l"(src), "r"(sz));
}

#define ASTAGE 16384
#define BSTAGE 4096
#define STAGE  (ASTAGE + BSTAGE)

__global__ __launch_bounds__(256, 2) void gemm_bf16_kernel(
        const __nv_bfloat16* __restrict__ A,
        const __nv_bfloat16* __restrict__ W,
        const float* __restrict__ bias,
        const float* __restrict__ res,
        __nv_bfloat16* __restrict__ Cb,
        float* __restrict__ Cf,
        int M, int N, int K, int mode) {
    __shared__ __align__(128) uint8_t smem[2 * STAGE];
    uint32_t sbase = (uint32_t)__cvta_generic_to_shared(smem);

    const int tid = threadIdx.x, warp = tid >> 5, lane = tid & 31;
    const int wm = warp & 3, wn = warp >> 2;        // 4m x 2n
    const int g = lane >> 2, tig = lane & 3;
    const int row0 = blockIdx.y * 256;
    const int col0 = blockIdx.x * 64;
    const int nstage = K / 32;

    float acc[4][4][4] = {};                        // [mi][ni][quad]

    // b-frag ldmatrix lane mapping
    const int quad = lane >> 3;
    const int rr = (quad & 1) * 8 + (lane & 7);
    const int kbq = (quad >> 1) * 16;
    // a-frag ldmatrix lane mapping
    const int ar = lane & 15, ac = (lane >> 4) * 16;
    // loader indices
    const int lm = tid >> 2, lc = tid & 3;

    // prologue: stage 0
    {
        uint32_t aB = sbase, bB = sbase + ASTAGE;
        #pragma unroll
        for (int j = 0; j < 4; j++) {
            int m = lm + j * 64;
            const void* src = A + (size_t)(row0 + m) * K + lc * 8;
            cpasync16(aB + swz(m, lc * 16), src, (row0 + m < M) ? 16 : 0);
        }
        cpasync16(bB + swz(lm, lc * 16), W + (size_t)(col0 + lm) * K + lc * 8, 16);
        asm volatile("cp.async.commit_group;");
    }

    for (int s = 0; s < nstage; s++) {
        if (s + 1 < nstage) {
            int k0 = (s + 1) * 32;
            uint32_t aB = sbase + ((s + 1) & 1) * STAGE, bB = aB + ASTAGE;
            #pragma unroll
            for (int j = 0; j < 4; j++) {
                int m = lm + j * 64;
                const void* src = A + (size_t)(row0 + m) * K + k0 + lc * 8;
                cpasync16(aB + swz(m, lc * 16), src, (row0 + m < M) ? 16 : 0);
            }
            cpasync16(bB + swz(lm, lc * 16), W + (size_t)(col0 + lm) * K + k0 + lc * 8, 16);
            asm volatile("cp.async.commit_group;");
            asm volatile("cp.async.wait_group 1;");
        } else {
            asm volatile("cp.async.wait_group 0;");
        }
        __syncthreads();

        uint32_t aB = sbase + (s & 1) * STAGE, bB = aB + ASTAGE;
        #pragma unroll
        for (int ks = 0; ks < 2; ks++) {
            uint32_t afr[4][4], bfr[4][2];
            #pragma unroll
            for (int mi = 0; mi < 4; mi++)
                ldsm4(afr[mi], aB + swz(wm * 64 + mi * 16 + ar, ks * 32 + ac));
            #pragma unroll
            for (int np = 0; np < 2; np++) {
                uint32_t r4[4];
                ldsm4(r4, bB + swz(wn * 32 + np * 16 + rr, ks * 32 + kbq));
                bfr[np * 2 + 0][0] = r4[0]; bfr[np * 2 + 0][1] = r4[2];
                bfr[np * 2 + 1][0] = r4[1]; bfr[np * 2 + 1][1] = r4[3];
            }
            #pragma unroll
            for (int mi = 0; mi < 4; mi++)
                #pragma unroll
                for (int ni = 0; ni < 4; ni++)
                    mma_bf16(acc[mi][ni], afr[mi], bfr[ni][0], bfr[ni][1]);
        }
        __syncthreads();
    }

    // epilogue
    #pragma unroll
    for (int mi = 0; mi < 4; mi++) {
        #pragma unroll
        for (int hi = 0; hi < 2; hi++) {
            int r = row0 + wm * 64 + mi * 16 + g + hi * 8;
            if (r >= M) continue;
            #pragma unroll
            for (int ni = 0; ni < 4; ni++) {
                int c = col0 + wn * 32 + ni * 8 + 2 * tig;
                float v0 = acc[mi][ni][hi * 2 + 0] + bias[c];
                float v1 = acc[mi][ni][hi * 2 + 1] + bias[c + 1];
                if (mode == 1) {
                    v0 = 0.5f * v0 * (1.0f + erff(v0 * 0.70710678118654752440f));
                    v1 = 0.5f * v1 * (1.0f + erff(v1 * 0.70710678118654752440f));
                }
                if (mode == 2) {
                    const float2 rv = *(const float2*)(res + (size_t)r * N + c);
                    *(float2*)(Cf + (size_t)r * N + c) = make_float2(v0 + rv.x, v1 + rv.y);
                } else {
                    *(__nv_bfloat162*)(Cb + (size_t)r * N + c) = __floats2bfloat162_rn(v0, v1);
                }
            }
        }
    }
}

// ---------------- kernel 3: tensor-core windowed attention ----------------
// block = (window, head), 288 threads = 9 warps, warp = 16 rows.
__device__ __forceinline__ uint32_t swa(uint32_t base, int row, int chunk) {
    return base + row * 64 + ((chunk ^ ((row >> 1) & 3)) << 4);
}

__global__ __launch_bounds__(288, 2) void attn_kernel() {
    __shared__ __align__(128) __nv_bfloat16 sQ[144 * 32];
    __shared__ __align__(128) __nv_bfloat16 sK[144 * 32];
    __shared__ __align__(128) __nv_bfloat16 sV[144 * 32];

    const int blk = blockIdx.x;
    const int gwin = blk / HEADS, head = blk % HEADS;
    const int ilon = gwin / NW, iw = gwin % NW;
    const int tid = threadIdx.x;
    const size_t base = (size_t)gwin * NTOK;

    {
        const __nv_bfloat16* tb = g_qkv + base * 576 + head * 32;
        for (int i = tid; i < 576; i += 288) {
            int n = i >> 2, c = i & 3;
            int off = n * 32 + ((c ^ ((n >> 1) & 3)) << 3);
            const __nv_bfloat16* tp = tb + (size_t)n * 576 + c * 8;
            *(uint4*)(sQ + off) = *(const uint4*)(tp);
            *(uint4*)(sK + off) = *(const uint4*)(tp + 192);
            *(uint4*)(sV + off) = *(const uint4*)(tp + 384);
        }
    }
    __syncthreads();

    const uint32_t qB = (uint32_t)__cvta_generic_to_shared(sQ);
    const uint32_t kB = (uint32_t)__cvta_generic_to_shared(sK);
    const uint32_t vB = (uint32_t)__cvta_generic_to_shared(sV);

    const int warp = tid >> 5, lane = tid & 31;
    const int g = lane >> 2, tig = lane & 3;
    const int m0 = warp * 16;

    uint32_t aq[2][4];
    #pragma unroll
    for (int kq = 0; kq < 2; kq++)
        ldsm4(aq[kq], swa(qB, m0 + (lane & 15), kq * 2 + (lane >> 4)));

    const __nv_bfloat16* bm = g_bmask
        + ((size_t)((ilon == 14 ? 1 : 0) * 384 + iw * HEADS + head)) * (NTOK * NTOK);
    const int r0 = m0 + g, r1 = r0 + 8;

    float den0 = 0.f, den1 = 0.f;
    float o[4][4] = {};

    #pragma unroll
    for (int ph = 0; ph < 2; ph++) {
        const int ntS = ph ? 10 : 0, ntE = ph ? 18 : 10;
        const int kcS = ph ? 5 : 0,  kcE = ph ? 9 : 5;

        float acc[10][4];
        #pragma unroll
        for (int j = 0; j < 10; j++)
            #pragma unroll
            for (int q = 0; q < 4; q++) acc[j][q] = 0.f;

        for (int nt = ntS; nt < ntE; nt++) {
            uint32_t bk[4];
            ldsm4(bk, swa(kB, nt * 8 + (lane & 7), lane >> 3));
            mma_bf16(acc[nt - ntS], aq[0], bk[0], bk[1]);
            mma_bf16(acc[nt - ntS], aq[1], bk[2], bk[3]);
        }

        uint32_t paLo[10], paHi[10];
        for (int nt = ntS; nt < ntE; nt++) {
            int j = nt - ntS;
            int c0 = nt * 8 + 2 * tig;
            __nv_bfloat162 b0 = *(const __nv_bfloat162*)(bm + (size_t)r0 * 144 + c0);
            __nv_bfloat162 b1 = *(const __nv_bfloat162*)(bm + (size_t)r1 * 144 + c0);
            float p0 = __expf(fmaf(acc[j][0], QKSCALE, __bfloat162float(b0.x)));
            float p1 = __expf(fmaf(acc[j][1], QKSCALE, __bfloat162float(b0.y)));
            float p2 = __expf(fmaf(acc[j][2], QKSCALE, __bfloat162float(b1.x)));
            float p3 = __expf(fmaf(acc[j][3], QKSCALE, __bfloat162float(b1.y)));
            den0 += p0 + p1; den1 += p2 + p3;
            paLo[j] = pack_bf2(p0, p1);
            paHi[j] = pack_bf2(p2, p3);
        }

        for (int kc = kcS; kc < kcE; kc++) {
            int j2 = 2 * (kc - kcS);
            uint32_t A[4] = {paLo[j2], paHi[j2], paLo[j2 + 1], paHi[j2 + 1]};
            #pragma unroll
            for (int np = 0; np < 2; np++) {
                uint32_t bv[4];
                ldsm4t(bv, swa(vB, kc * 16 + ((lane >> 3) & 1) * 8 + (lane & 7),
                               np * 2 + (lane >> 4)));
                mma_bf16(o[np * 2 + 0], A, bv[0], bv[1]);
                mma_bf16(o[np * 2 + 1], A, bv[2], bv[3]);
            }
        }
    }

    den0 += __shfl_xor_sync(0xffffffffu, den0, 1);
    den0 += __shfl_xor_sync(0xffffffffu, den0, 2);
    den1 += __shfl_xor_sync(0xffffffffu, den1, 1);
    den1 += __shfl_xor_sync(0xffffffffu, den1, 2);
    float inv0 = 1.f / den0, inv1 = 1.f / den1;

    __nv_bfloat16* ob = g_att + base * DIM + head * HD;
    #pragma unroll
    for (int nt4 = 0; nt4 < 4; nt4++) {
        int col = nt4 * 8 + 2 * tig;
        *(__nv_bfloat162*)(ob + (size_t)r0 * DIM + col) =
            __floats2bfloat162_rn(o[nt4][0] * inv0, o[nt4][1] * inv0);
        *(__nv_bfloat162*)(ob + (size_t)r1 * DIM + col) =
            __floats2bfloat162_rn(o[nt4][2] * inv1, o[nt4][3] * inv1);
    }
}

// ---------------- kernel 5: scatter + residual + LN2 ----------------
__global__ void resid_ln2_kernel(const float* __restrict__ x,
                                 const float* __restrict__ w2,
                                 const float* __restrict__ b2) {
    int warp = threadIdx.x >> 5, lane = threadIdx.x & 31;
    int t = blockIdx.x * 8 + warp;
    int lon = t % 180;
    int lat = (t / 180) % 91;
    int pl  = t / (180 * 91);
    int pl_r  = (pl + 7) & 7;
    int lat_r = lat - 1; if (lat_r < 0) lat_r += 96;
    int lon_r = lon - 6; if (lon_r < 0) lon_r += 180;
    int ilon = lon_r / 12, ww = lon_r % 12;
    int ipl = pl_r >> 1,  z  = pl_r & 1;
    int ilat = lat_r / 6, hh = lat_r % 6;
    size_t wt = (size_t)(ilon * NW + ipl * 16 + ilat) * NTOK + z * 72 + hh * 12 + ww;

    const float* xs = x + (size_t)t * DIM;
    const __nv_bfloat16* ps = g_proj + wt * DIM;
    float v[6]; float s = 0.f, qq = 0.f;
    #pragma unroll
    for (int j = 0; j < 6; j++) {
        int c = lane + 32 * j;
        v[j] = xs[c] + __bfloat162float(ps[c]);
        s += v[j]; qq += v[j] * v[j];
    }
    #pragma unroll
    for (int o = 16; o > 0; o >>= 1) {
        s  += __shfl_xor_sync(0xffffffffu, s, o);
        qq += __shfl_xor_sync(0xffffffffu, qq, o);
    }
    float mean = s * (1.f / 192.f);
    float var  = qq * (1.f / 192.f) - mean * mean;
    float rs = rsqrtf(var + EPSLN);
    #pragma unroll
    for (int j = 0; j < 6; j++) {
        int c = lane + 32 * j;
        g_x1[(size_t)t * DIM + c] = v[j];
        g_h2[(size_t)t * DIM + c] = __float2bfloat16((v[j] - mean) * rs * w2[c] + b2[c]);
    }
}

// ---------------- launcher ----------------
extern "C" void kernel_launch(void* const* d_in, const int* in_sizes, int n_in,
                              void* d_out, int out_size) {
    const float* x     = (const float*)d_in[0];
    const float* n1w   = (const float*)d_in[1];
    const float* n1b   = (const float*)d_in[2];
    const float* qkvw  = (const float*)d_in[3];
    const float* qkvb  = (const float*)d_in[4];
    const float* btab  = (const float*)d_in[5];
    const float* projw = (const float*)d_in[6];
    const float* projb = (const float*)d_in[7];
    const float* n2w   = (const float*)d_in[8];
    const float* n2b   = (const float*)d_in[9];
    const float* fc1w  = (const float*)d_in[10];
    const float* fc1b  = (const float*)d_in[11];
    const float* fc2w  = (const float*)d_in[12];
    const float* fc2b  = (const float*)d_in[13];
    float* out = (float*)d_out;

    __nv_bfloat16 *p_h, *p_qkv, *p_att, *p_proj, *p_h2, *p_fc1;
    __nv_bfloat16 *p_wq, *p_wp, *p_w1, *p_w2;
    float *p_x1;
    cudaGetSymbolAddress((void**)&p_h,    g_h);
    cudaGetSymbolAddress((void**)&p_qkv,  g_qkv);
    cudaGetSymbolAddress((void**)&p_att,  g_att);
    cudaGetSymbolAddress((void**)&p_proj, g_proj);
    cudaGetSymbolAddress((void**)&p_x1,   g_x1);
    cudaGetSymbolAddress((void**)&p_h2,   g_h2);
    cudaGetSymbolAddress((void**)&p_fc1,  g_fc1);
    cudaGetSymbolAddress((void**)&p_wq,   g_wq);
    cudaGetSymbolAddress((void**)&p_wp,   g_wp);
    cudaGetSymbolAddress((void**)&p_w1,   g_w1);
    cudaGetSymbolAddress((void**)&p_w2,   g_w2);

    // weight conversion + bias transpose + combined bias/mask matrices
    cvt_kernel<<<(576 * 192 + 255) / 256, 256>>>(qkvw,  p_wq, 576 * 192);
    cvt_kernel<<<(192 * 192 + 255) / 256, 256>>>(projw, p_wp, 192 * 192);
    cvt_kernel<<<(768 * 192 + 255) / 256, 256>>>(fc1w,  p_w1, 768 * 192);
    cvt_kernel<<<(192 * 768 + 255) / 256, 256>>>(fc2w,  p_w2, 192 * 768);
    biasT_kernel<<<3312, 384>>>(btab);
    bmask_kernel<<<768, 256>>>();

    // 1. LN1 + window partition
    ln1_window_kernel<<<WTOK / 8, 256>>>(x, n1w, n1b);

    // 2. QKV gemm: [WTOK,192] x [576,192]^T
    gemm_bf16_kernel<<<dim3(9, WTOK / 256), 256>>>(
        p_h, p_wq, qkvb, nullptr, p_qkv, nullptr, WTOK, 576, 192, 0);

    // 3. attention
    attn_kernel<<<NLON * NW * HEADS, 288>>>();

    // 4. proj gemm
    gemm_bf16_kernel<<<dim3(3, WTOK / 256), 256>>>(
        p_att, p_wp, projb, nullptr, p_proj, nullptr, WTOK, 192, 192, 0);

    // 5. scatter + residual + LN2
    resid_ln2_kernel<<<LTOK / 8, 256>>>(x, n2w, n2b);

    // 6. fc1 gemm + gelu
    gemm_bf16_kernel<<<dim3(12, (LTOK + 255) / 256), 256>>>(
        p_h2, p_w1, fc1b, nullptr, p_fc1, nullptr, LTOK, 768, 192, 1);

    // 7. fc2 gemm + residual -> out
    gemm_bf16_kernel<<<dim3(3, (LTOK + 255) / 256), 256>>>(
        p_fc1, p_w2, fc2b, p_x1, nullptr, out, LTOK, 192, 768, 2);
}